// round 7
// baseline (speedup 1.0000x reference)
#include <cuda_runtime.h>
#include <cooperative_groups.h>
#include <math.h>
namespace cg = cooperative_groups;

#define BB 32
#define NT 512
#define DH 128
#define DI 256
#define BN (BB*NT)
#define SMAT (NT*NT)
#define NHS ((long)NT*DH)

// ---------------- static device scratch ----------------
__device__ float g_H0[BN*DH];
__device__ float g_M0[BN*DH];
__device__ float g_Ha[BN*DH];
__device__ float g_Hb[BN*DH];
__device__ float g_Ma[BN*DH];
__device__ float g_Mb[BN*DH];
__device__ float g_T1[BN*DH];
__device__ float g_T2[BN*DH];
__device__ float g_Lm[(long)BB*SMAT];
__device__ float g_Li[(long)BB*SMAT];
__device__ float g_c[BB];
__device__ float g_pm[BB*8];
__device__ float g_ldp[BB*16];
__device__ float g_part[BB*256];

// ---------------- shared memory union ----------------
struct SG { float As[16][65]; float Bs[16][65]; };
struct SI { float T[32][33]; float D[32][33]; };
struct SY { float Lt[32][33]; float dg[32]; float l0[32]; float red[256]; };
union USm { SG g; SI s; SY y; float red[256]; };

// ---------------- 64x64x16 GEMM tile (256 threads) ----------------
// EPI: 0 C=acc | 1 C-=acc | 2 C=relu(C0+acc) | 3 C=acc+bias, C2=relu(C)
template<bool TRA,bool TRB,int EPI>
__device__ __forceinline__ void gemm_tile(USm* sm,
    const float* __restrict__ A,const float* __restrict__ B,
    float* __restrict__ C,const float* __restrict__ C0,
    const float* __restrict__ bias,float* __restrict__ C2,
    int m0,int n0,int M,int N,int K,int lda,int ldb,int ldc)
{
    int t=threadIdx.x, ty=t>>4, tx=t&15;
    float acc[4][4];
    #pragma unroll
    for(int i=0;i<4;i++)
        #pragma unroll
        for(int j=0;j<4;j++) acc[i][j]=0.f;
    for(int k0=0;k0<K;k0+=16){
        #pragma unroll
        for(int i=t;i<1024;i+=256){
            int kk,m;
            if(!TRA){ kk=i&15; m=i>>4; } else { m=i&63; kk=i>>6; }
            float v=0.f;
            if(m0+m<M) v=(!TRA)? A[(long)(m0+m)*lda+k0+kk] : A[(long)(k0+kk)*lda+m0+m];
            sm->g.As[kk][m]=v;
        }
        #pragma unroll
        for(int i=t;i<1024;i+=256){
            int kk,n;
            if(!TRB){ n=i&63; kk=i>>6; } else { kk=i&15; n=i>>4; }
            float v=0.f;
            if(n0+n<N) v=(!TRB)? B[(long)(k0+kk)*ldb+n0+n] : B[(long)(n0+n)*ldb+k0+kk];
            sm->g.Bs[kk][n]=v;
        }
        __syncthreads();
        #pragma unroll
        for(int kk=0;kk<16;kk++){
            float a[4],bv[4];
            #pragma unroll
            for(int i=0;i<4;i++) a[i]=sm->g.As[kk][ty+i*16];
            #pragma unroll
            for(int j=0;j<4;j++) bv[j]=sm->g.Bs[kk][tx+j*16];
            #pragma unroll
            for(int i=0;i<4;i++)
                #pragma unroll
                for(int j=0;j<4;j++) acc[i][j]=fmaf(a[i],bv[j],acc[i][j]);
        }
        __syncthreads();
    }
    #pragma unroll
    for(int i=0;i<4;i++){
        int m=m0+ty+i*16;
        if(m<M){
            #pragma unroll
            for(int j=0;j<4;j++){
                int n=n0+tx+j*16;
                if(n<N){
                    long off=(long)m*ldc+n;
                    float v=acc[i][j];
                    if(EPI==0) C[off]=v;
                    else if(EPI==1) C[off]-=v;
                    else if(EPI==2) C[off]=fmaxf(C0[off]+v,0.f);
                    else { float w=v+bias[n]; C[off]=w; C2[off]=fmaxf(w,0.f); }
                }
            }
        }
    }
}

// ---------------- the mega kernel ----------------
__global__ void __launch_bounds__(256) mega_k(
    const float* __restrict__ Xh,const float* __restrict__ Xm,
    const int* __restrict__ len,
    const float* __restrict__ Wh,const float* __restrict__ bh,
    const float* __restrict__ Wm,const float* __restrict__ bm,
    const float* __restrict__ V,
    float* __restrict__ S,float* __restrict__ logZ,
    float* __restrict__ Y,float* __restrict__ entr)
{
    cg::grid_group grid=cg::this_grid();
    __shared__ USm sm;
    const int t=threadIdx.x;
    const int GB=gridDim.x;

    float *H0=g_H0,*M0=g_M0,*T1=g_T1,*T2=g_T2,*Lm=g_Lm,*Li=g_Li;
    float *Hc=g_Ha,*Mc=g_Ma,*Hx=g_Hb,*Mx=g_Mb;

    // ---- P0: H0 = Xh@Wh^T+bh (and Ha=relu), M0 likewise ----
    for(int task=blockIdx.x;task<1024;task+=GB){
        int which=task>>9, sub=task&511, mt=sub>>1, nt=sub&1;
        if(which==0)
            gemm_tile<false,true,3>(&sm,Xh,Wh,H0,nullptr,bh,Hc, mt*64,nt*64,BN,DH,DI,DI,DI,DH);
        else
            gemm_tile<false,true,3>(&sm,Xm,Wm,M0,nullptr,bm,Mc, mt*64,nt*64,BN,DH,DI,DI,DI,DH);
    }
    grid.sync();

    for(int it=0;it<10;it++){
        // ---- P1: T1 = Hc @ V ----
        for(int task=blockIdx.x;task<512;task+=GB){
            int mt=task>>1, nt=task&1;
            gemm_tile<false,false,0>(&sm,Hc,V,T1,nullptr,nullptr,nullptr,
                mt*64,nt*64,BN,DH,DH,DH,DH,DH);
        }
        grid.sync();
        // ---- P2: S = T1 @ Mc^T (batched) ----
        for(int task=blockIdx.x;task<2048;task+=GB){
            int b=task>>6, s2=task&63, mt=s2>>3, nt=s2&7;
            gemm_tile<false,true,0>(&sm,T1+(long)b*NHS,Mc+(long)b*NHS,S+(long)b*SMAT,
                nullptr,nullptr,nullptr, mt*64,nt*64,NT,NT,DH,DH,DH,NT);
        }
        grid.sync();
        // ---- P3: per-batch max partials (8 slices of 64 rows) ----
        for(int task=blockIdx.x;task<256;task+=GB){
            int b=task>>3, sl=task&7;
            int L=len[b];
            const float* Sb=S+(long)b*SMAT;
            float mx=-1e30f;
            for(int r=sl*64;r<sl*64+64;r++){
                if(r>L) break;
                for(int m=t+1;m<=L;m+=256)
                    if(m!=r) mx=fmaxf(mx,Sb[(long)r*NT+m]);
            }
            sm.red[t]=mx; __syncthreads();
            for(int s=128;s>0;s>>=1){ if(t<s) sm.red[t]=fmaxf(sm.red[t],sm.red[t+s]); __syncthreads(); }
            if(t==0) g_pm[b*8+sl]=sm.red[0];
            __syncthreads();
        }
        grid.sync();
        // ---- P4: c, colsum (regs), buildL (block per batch) ----
        for(int task=blockIdx.x;task<BB;task+=GB){
            int b=task, L=len[b];
            float c=-1e30f;
            for(int k2=0;k2<8;k2++) c=fmaxf(c,g_pm[b*8+k2]);
            if(t==0) g_c[b]=c;
            const float* Sb=S+(long)b*SMAT;
            float* Lb=Lm+(long)b*SMAT;
            int j0=t, j1=t+256;
            int mA=j0+1, mB=j1+1;   // modifier indices for the two owned columns
            float cs0=0.f, cs1=0.f;
            for(int h=0;h<=L;h++){
                if(mA<=L && h!=mA) cs0+=expf(Sb[(long)h*NT+mA]-c);
                if(mB<NT && mB<=L && h!=mB) cs1+=expf(Sb[(long)h*NT+mB]-c);
            }
            auto lval=[&](int i,int j,int m,float cs)->float{
                if(i==NT-1) return (j==NT-1)?1.f:0.f;
                if(j==NT-1) return 0.f;
                float pad=(m>L)?1.f:0.f;
                if(i==0){
                    float a=(m<=L)?expf(Sb[m]-c):0.f;
                    return a+((j==0)?pad:0.f);
                }
                if(i==j) return cs+pad;
                int h=i+1;
                return (h<=L&&m<=L)? -expf(Sb[(long)h*NT+m]-c) : 0.f;
            };
            for(int i=0;i<NT;i++){
                Lb[(long)i*NT+j0]=lval(i,j0,mA,cs0);
                Lb[(long)i*NT+j1]=lval(i,j1,mB,cs1);
            }
        }
        grid.sync();
        // ---- P5: blocked LU, 16 panels x (A: diag+trsm, B: schur) ----
        for(int k=0;k<16;k++){
            int k0=k*32, rem=NT-k0-32;
            // Phase A: each block factors diag redundantly in smem, then its trsm role
            for(int task=blockIdx.x;task<128;task+=GB){
                int b=task>>2, role=task&3;
                float* Lb=Lm+(long)b*SMAT;
                for(int i=t;i<1024;i+=256) sm.s.D[i>>5][i&31]=Lb[(long)(k0+(i>>5))*NT+k0+(i&31)];
                __syncthreads();
                if(t<32){
                    for(int j=0;j<32;j++){
                        float inv=1.f/sm.s.D[j][j];
                        if(t>j){
                            float l=sm.s.D[t][j]*inv;
                            sm.s.D[t][j]=l;
                            for(int jj=j+1;jj<32;jj++) sm.s.D[t][jj]-=l*sm.s.D[j][jj];
                        }
                        __syncwarp();
                    }
                }
                __syncthreads();
                if(role==0){
                    for(int i=t;i<1024;i+=256) Lb[(long)(k0+(i>>5))*NT+k0+(i&31)]=sm.s.D[i>>5][i&31];
                    if(t==0){
                        float s=0.f;
                        for(int j=0;j<32;j++) s+=logf(fabsf(sm.s.D[j][j]));
                        g_ldp[b*16+k]=s;
                    }
                }
                if(role<2){
                    int row=k0+32+role*256+t;
                    if(row<NT){
                        float x[32];
                        #pragma unroll
                        for(int j=0;j<32;j++) x[j]=Lb[(long)row*NT+k0+j];
                        #pragma unroll
                        for(int j=0;j<32;j++){
                            float xj=x[j];
                            #pragma unroll
                            for(int l=0;l<32;l++) if(l<j) xj-=x[l]*sm.s.D[l][j];
                            x[j]=xj/sm.s.D[j][j];
                        }
                        #pragma unroll
                        for(int j=0;j<32;j++) Lb[(long)row*NT+k0+j]=x[j];
                    }
                } else {
                    int cc=k0+32+(role-2)*256+t;
                    if(cc<NT){
                        float x[32];
                        #pragma unroll
                        for(int i=0;i<32;i++) x[i]=Lb[(long)(k0+i)*NT+cc];
                        #pragma unroll
                        for(int i=1;i<32;i++){
                            float xi=x[i];
                            #pragma unroll
                            for(int j=0;j<32;j++) if(j<i) xi-=sm.s.D[i][j]*x[j];
                            x[i]=xi;
                        }
                        #pragma unroll
                        for(int i=0;i<32;i++) Lb[(long)(k0+i)*NT+cc]=x[i];
                    }
                }
                __syncthreads();
            }
            grid.sync();
            // Phase B: Schur update
            int nb=(rem+63)>>6;
            int ntasks=BB*nb*nb;
            for(int task=blockIdx.x;task<ntasks;task+=GB){
                int b=task/(nb*nb), s2=task%(nb*nb), mt=s2/nb, nt2=s2%nb;
                float* Lb=Lm+(long)b*SMAT;
                gemm_tile<false,false,1>(&sm, Lb+(long)(k0+32)*NT+k0, Lb+(long)k0*NT+(k0+32),
                    Lb+(long)(k0+32)*NT+(k0+32), nullptr,nullptr,nullptr,
                    mt*64,nt2*64,rem,rem,32,NT,NT,NT);
            }
            grid.sync();
        }
        // ---- P6: inverse forward solve  L z = I (column-independent) ----
        for(int task=blockIdx.x;task<64;task+=GB){
            int b=task>>1, cb=task&1;
            const float* Lb=Lm+(long)b*SMAT;
            float* Zb=Li+(long)b*SMAT;
            int c=cb*256+t;
            for(int ib=cb*8;ib<16;ib++){
                float acc[32];
                #pragma unroll
                for(int r=0;r<32;r++) acc[r]=(ib*32+r==c)?1.f:0.f;
                for(int kb=cb*8;kb<ib;kb++){
                    for(int i=t;i<1024;i+=256) sm.s.T[i>>5][i&31]=Lb[(long)(ib*32+(i>>5))*NT+kb*32+(i&31)];
                    __syncthreads();
                    #pragma unroll 4
                    for(int q=0;q<32;q++){
                        float xq=Zb[(long)(kb*32+q)*NT+c];
                        #pragma unroll
                        for(int r=0;r<32;r++) acc[r]-=sm.s.T[r][q]*xq;
                    }
                    __syncthreads();
                }
                for(int i=t;i<1024;i+=256) sm.s.D[i>>5][i&31]=Lb[(long)(ib*32+(i>>5))*NT+ib*32+(i&31)];
                __syncthreads();
                #pragma unroll
                for(int r=1;r<32;r++){
                    float a=acc[r];
                    #pragma unroll
                    for(int q=0;q<32;q++) if(q<r) a-=sm.s.D[r][q]*acc[q];
                    acc[r]=a;
                }
                #pragma unroll
                for(int r=0;r<32;r++) Zb[(long)(ib*32+r)*NT+c]=acc[r];
                __syncthreads();
            }
        }
        grid.sync();
        // ---- P7: inverse backward solve  U x = z ----
        for(int task=blockIdx.x;task<64;task+=GB){
            int b=task>>1, cb=task&1;
            const float* Lb=Lm+(long)b*SMAT;
            float* Zb=Li+(long)b*SMAT;
            int c=cb*256+t;
            for(int ib=15;ib>=0;ib--){
                float acc[32];
                if(ib>=cb*8){
                    #pragma unroll
                    for(int r=0;r<32;r++) acc[r]=Zb[(long)(ib*32+r)*NT+c];
                } else {
                    #pragma unroll
                    for(int r=0;r<32;r++) acc[r]=0.f;
                }
                for(int kb=ib+1;kb<16;kb++){
                    for(int i=t;i<1024;i+=256) sm.s.T[i>>5][i&31]=Lb[(long)(ib*32+(i>>5))*NT+kb*32+(i&31)];
                    __syncthreads();
                    #pragma unroll 4
                    for(int q=0;q<32;q++){
                        float xq=Zb[(long)(kb*32+q)*NT+c];
                        #pragma unroll
                        for(int r=0;r<32;r++) acc[r]-=sm.s.T[r][q]*xq;
                    }
                    __syncthreads();
                }
                for(int i=t;i<1024;i+=256) sm.s.D[i>>5][i&31]=Lb[(long)(ib*32+(i>>5))*NT+ib*32+(i&31)];
                __syncthreads();
                #pragma unroll
                for(int r=31;r>=0;r--){
                    float a=acc[r];
                    #pragma unroll
                    for(int q=0;q<32;q++) if(q>r) a-=sm.s.D[r][q]*acc[q];
                    acc[r]=a/sm.s.D[r][r];
                }
                #pragma unroll
                for(int r=0;r<32;r++) Zb[(long)(ib*32+r)*NT+c]=acc[r];
                __syncthreads();
            }
        }
        grid.sync();
        // ---- P8: marginals Y + entropy partials ----
        for(int task=blockIdx.x;task<8192;task+=GB){
            int b=task>>8, s2=task&255, hy=s2>>4, mxt=s2&15;
            int m0=mxt*32, h0=hy*32;
            const float* Lb=Li+(long)b*SMAT;
            const float* Sb=S+(long)b*SMAT;
            float* Yb=Y+(long)b*SMAT;
            int L=len[b]; float cb=g_c[b];
            for(int i=t;i<1024;i+=256){
                int mi=i>>5, hi=i&31;
                int m=m0+mi, h=h0+hi;
                sm.y.Lt[mi][hi]=(m>=1&&h>=1)? Lb[(long)(m-1)*NT+(h-1)] : 0.f;
            }
            if(t<32){
                int m=m0+t;
                sm.y.dg[t]=(m>=2)? Lb[(long)(m-1)*NT+(m-1)] : 0.f;
                sm.y.l0[t]=(m>=1)? Lb[(long)(m-1)*NT] : 0.f;
            }
            __syncthreads();
            float yts=0.f;
            int mi=t&31, hb2=t>>5;
            int m=m0+mi;
            #pragma unroll
            for(int p=0;p<4;p++){
                int hi=hb2+p*8;
                int h=h0+hi;
                float y=0.f;
                float sv=Sb[(long)h*NT+m];
                if(m>=1&&m<=L&&h<=L&&h!=m){
                    float a=expf(sv-cb);
                    float val=(h==0)? (sm.y.l0[mi]+sm.y.dg[mi])
                                    : (sm.y.dg[mi]-((h>=2)? sm.y.Lt[mi][hi]:0.f));
                    y=a*val; yts+=y*sv;
                }
                Yb[(long)h*NT+m]=y;
            }
            sm.y.red[t]=yts; __syncthreads();
            for(int s=128;s>0;s>>=1){ if(t<s) sm.y.red[t]+=sm.y.red[t+s]; __syncthreads(); }
            if(t==0) g_part[(long)b*256+hy*16+mxt]=sm.y.red[0];
            __syncthreads();
        }
        grid.sync();
        // ---- P9 (finalize) + P10 (feature GEMMs) fused ----
        int np=(it<9)? 1056 : 32;
        for(int task=blockIdx.x;task<np;task+=GB){
            if(task<32){
                int b=task;
                sm.red[t]=g_part[(long)b*256+t];
                __syncthreads();
                for(int s=128;s>0;s>>=1){ if(t<s) sm.red[t]+=sm.red[t+s]; __syncthreads(); }
                if(t==0){
                    float ld=0.f;
                    for(int kk=0;kk<16;kk++) ld+=g_ldp[b*16+kk];
                    float lz=ld+(float)len[b]*g_c[b];
                    logZ[b]=lz; entr[b]=lz-sm.red[0];
                }
                __syncthreads();
            } else {
                int t2=task-32;
                int which=t2>>9, sub=t2&511;
                int b=sub>>4, s3=sub&15, mt=s3>>1, nt2=s3&1;
                if(which==0)
                    gemm_tile<false,false,0>(&sm,Y+(long)b*SMAT,Mc+(long)b*NHS,T1+(long)b*NHS,
                        nullptr,nullptr,nullptr, mt*64,nt2*64,NT,DH,NT,NT,DH,DH);
                else
                    gemm_tile<true,false,0>(&sm,Y+(long)b*SMAT,Hc+(long)b*NHS,T2+(long)b*NHS,
                        nullptr,nullptr,nullptr, mt*64,nt2*64,NT,DH,NT,NT,DH,DH);
            }
        }
        grid.sync();
        // ---- P11: Hx = relu(H0 + T1@V^T), Mx = relu(M0 + T2@V) ----
        if(it<9){
            for(int task=blockIdx.x;task<1024;task+=GB){
                int which=task>>9, sub=task&511, mt=sub>>1, nt2=sub&1;
                if(which==0)
                    gemm_tile<false,true,2>(&sm,T1,V,Hx,H0,nullptr,nullptr,
                        mt*64,nt2*64,BN,DH,DH,DH,DH,DH);
                else
                    gemm_tile<false,false,2>(&sm,T2,V,Mx,M0,nullptr,nullptr,
                        mt*64,nt2*64,BN,DH,DH,DH,DH,DH);
            }
            grid.sync();
            float* tmp;
            tmp=Hc;Hc=Hx;Hx=tmp;
            tmp=Mc;Mc=Mx;Mx=tmp;
        }
    }
}

// ---------------- host launch ----------------
extern "C" void kernel_launch(void* const* d_in, const int* in_sizes, int n_in,
                              void* d_out, int out_size){
    const float* Xh=(const float*)d_in[0];
    const float* Xm=(const float*)d_in[1];
    const int*   len=(const int*)d_in[2];
    const float* Wh=(const float*)d_in[3];
    const float* bh=(const float*)d_in[4];
    const float* Wm=(const float*)d_in[5];
    const float* bm=(const float*)d_in[6];
    const float* V =(const float*)d_in[7];
    float* out=(float*)d_out;
    float* S   =out;
    float* logZ=out+(long)BB*SMAT;
    float* Y   =logZ+BB;
    float* entr=Y+(long)BB*SMAT;

    int dev=0; cudaGetDevice(&dev);
    int sms=0; cudaDeviceGetAttribute(&sms,cudaDevAttrMultiProcessorCount,dev);
    int occ=0; cudaOccupancyMaxActiveBlocksPerMultiprocessor(&occ,mega_k,256,0);
    if(occ<1) occ=1;
    int nblk=sms*occ;

    void* args[]={(void*)&Xh,(void*)&Xm,(void*)&len,(void*)&Wh,(void*)&bh,
                  (void*)&Wm,(void*)&bm,(void*)&V,
                  (void*)&S,(void*)&logZ,(void*)&Y,(void*)&entr};
    cudaLaunchCooperativeKernel((const void*)mega_k,dim3(nblk),dim3(256),args,0,(cudaStream_t)0);
}

// round 8
// speedup vs baseline: 1.4047x; 1.4047x over previous
#include <cuda_runtime.h>
#include <cooperative_groups.h>
#include <math.h>
namespace cg = cooperative_groups;

#define BB 32
#define NT 512
#define DH 128
#define DI 256
#define BN (BB*NT)
#define SMAT (NT*NT)
#define NHS ((long)NT*DH)

// ---------------- static device scratch ----------------
__device__ float g_H0[BN*DH];
__device__ float g_M0[BN*DH];
__device__ float g_Ha[BN*DH];
__device__ float g_Hb[BN*DH];
__device__ float g_Ma[BN*DH];
__device__ float g_Mb[BN*DH];
__device__ float g_T1[BN*DH];
__device__ float g_T2[BN*DH];
__device__ float g_Lm[(long)BB*SMAT];
__device__ float g_Li[(long)BB*SMAT];
__device__ float g_c[BB];
__device__ float g_pm[BB*8];
__device__ float g_ldp[BB*16];
__device__ float g_part[BB*256];

// ---------------- shared memory union ----------------
struct SG { float As[2][16][68]; float Bs[2][16][68]; };
struct SI { float T4[4][32][33]; float R[3][32][65]; };
struct SY { float Lt[32][33]; float dg[32]; float l0[32]; float red[256]; };
union USm { SG g; SI s; SY y; float red[256]; };

// ---------------- 64x64x16 GEMM tile, double-buffered, float4 ----------------
// EPI: 0 C=acc | 1 C-=acc | 2 C=relu(C0+acc) | 3 C=acc+bias, C2=relu(C)
template<bool TRA,bool TRB,int EPI>
__device__ __forceinline__ void gemm_tile(USm* sm,
    const float* __restrict__ A,const float* __restrict__ B,
    float* __restrict__ C,const float* __restrict__ C0,
    const float* __restrict__ bias,float* __restrict__ C2,
    int m0,int n0,int M,int N,int K,int lda,int ldb,int ldc)
{
    const int t=threadIdx.x;
    const int ty=t>>4, tx=t&15;     // thread owns rows m0+ty*4.., cols n0+tx*4..
    float acc[4][4];
    #pragma unroll
    for(int i=0;i<4;i++)
        #pragma unroll
        for(int j=0;j<4;j++) acc[i][j]=0.f;

    auto ldA=[&](int kp)->float4{
        float4 v=make_float4(0.f,0.f,0.f,0.f);
        if(!TRA){ int row=t>>2, kq=t&3;
            if(m0+row<M) v=*reinterpret_cast<const float4*>(&A[(long)(m0+row)*lda + kp+kq*4]);
        } else { int kk=t>>4, mq=t&15;
            if(m0+mq*4<M) v=*reinterpret_cast<const float4*>(&A[(long)(kp+kk)*lda + m0+mq*4]);
        }
        return v;
    };
    auto stA=[&](int buf,float4 v){
        if(!TRA){ int row=t>>2, kq=t&3;
            sm->g.As[buf][kq*4+0][row]=v.x; sm->g.As[buf][kq*4+1][row]=v.y;
            sm->g.As[buf][kq*4+2][row]=v.z; sm->g.As[buf][kq*4+3][row]=v.w;
        } else { int kk=t>>4, mq=t&15;
            *reinterpret_cast<float4*>(&sm->g.As[buf][kk][mq*4])=v;
        }
    };
    auto ldB=[&](int kp)->float4{
        float4 v=make_float4(0.f,0.f,0.f,0.f);
        if(!TRB){ int kk=t>>4, nq=t&15;
            if(n0+nq*4<N) v=*reinterpret_cast<const float4*>(&B[(long)(kp+kk)*ldb + n0+nq*4]);
        } else { int row=t>>2, kq=t&3;
            if(n0+row<N) v=*reinterpret_cast<const float4*>(&B[(long)(n0+row)*ldb + kp+kq*4]);
        }
        return v;
    };
    auto stB=[&](int buf,float4 v){
        if(!TRB){ int kk=t>>4, nq=t&15;
            *reinterpret_cast<float4*>(&sm->g.Bs[buf][kk][nq*4])=v;
        } else { int row=t>>2, kq=t&3;
            sm->g.Bs[buf][kq*4+0][row]=v.x; sm->g.Bs[buf][kq*4+1][row]=v.y;
            sm->g.Bs[buf][kq*4+2][row]=v.z; sm->g.Bs[buf][kq*4+3][row]=v.w;
        }
    };

    const int nk=K>>4;
    stA(0,ldA(0)); stB(0,ldB(0));
    __syncthreads();
    for(int kb=0;kb<nk;kb++){
        int cur=kb&1;
        float4 pa,pb;
        bool more=(kb+1<nk);
        if(more){ pa=ldA((kb+1)<<4); pb=ldB((kb+1)<<4); }
        #pragma unroll
        for(int kk=0;kk<16;kk++){
            float4 a4=*reinterpret_cast<const float4*>(&sm->g.As[cur][kk][ty*4]);
            float4 b4=*reinterpret_cast<const float4*>(&sm->g.Bs[cur][kk][tx*4]);
            float a[4]={a4.x,a4.y,a4.z,a4.w};
            float b[4]={b4.x,b4.y,b4.z,b4.w};
            #pragma unroll
            for(int i=0;i<4;i++)
                #pragma unroll
                for(int j=0;j<4;j++) acc[i][j]=fmaf(a[i],b[j],acc[i][j]);
        }
        if(more){ stA(cur^1,pa); stB(cur^1,pb); }
        __syncthreads();
    }
    #pragma unroll
    for(int i=0;i<4;i++){
        int m=m0+ty*4+i;
        if(m<M){
            int n=n0+tx*4;
            if(n<N){
                long off=(long)m*ldc+n;
                float4 v=make_float4(acc[i][0],acc[i][1],acc[i][2],acc[i][3]);
                if(EPI==0) *reinterpret_cast<float4*>(&C[off])=v;
                else if(EPI==1){
                    float4 c=*reinterpret_cast<const float4*>(&C[off]);
                    c.x-=v.x; c.y-=v.y; c.z-=v.z; c.w-=v.w;
                    *reinterpret_cast<float4*>(&C[off])=c;
                } else if(EPI==2){
                    float4 c=*reinterpret_cast<const float4*>(&C0[off]);
                    c.x=fmaxf(c.x+v.x,0.f); c.y=fmaxf(c.y+v.y,0.f);
                    c.z=fmaxf(c.z+v.z,0.f); c.w=fmaxf(c.w+v.w,0.f);
                    *reinterpret_cast<float4*>(&C[off])=c;
                } else {
                    float4 bb=*reinterpret_cast<const float4*>(&bias[n]);
                    v.x+=bb.x; v.y+=bb.y; v.z+=bb.z; v.w+=bb.w;
                    *reinterpret_cast<float4*>(&C[off])=v;
                    float4 r=make_float4(fmaxf(v.x,0.f),fmaxf(v.y,0.f),fmaxf(v.z,0.f),fmaxf(v.w,0.f));
                    *reinterpret_cast<float4*>(&C2[off])=r;
                }
            }
        }
    }
}

// ---------------- the mega kernel ----------------
__global__ void __launch_bounds__(256) mega_k(
    const float* __restrict__ Xh,const float* __restrict__ Xm,
    const int* __restrict__ len,
    const float* __restrict__ Wh,const float* __restrict__ bh,
    const float* __restrict__ Wm,const float* __restrict__ bm,
    const float* __restrict__ V,
    float* __restrict__ S,float* __restrict__ logZ,
    float* __restrict__ Y,float* __restrict__ entr)
{
    cg::grid_group grid=cg::this_grid();
    __shared__ USm sm;
    const int t=threadIdx.x;
    const int GB=gridDim.x;

    float *H0=g_H0,*M0=g_M0,*T1=g_T1,*T2=g_T2,*Lm=g_Lm,*Li=g_Li;
    float *Hc=g_Ha,*Mc=g_Ma,*Hx=g_Hb,*Mx=g_Mb;

    // ---- P0: H0 = Xh@Wh^T+bh (Ha=relu), M0 likewise ----
    for(int task=blockIdx.x;task<1024;task+=GB){
        int which=task>>9, sub=task&511, mt=sub>>1, nt=sub&1;
        if(which==0)
            gemm_tile<false,true,3>(&sm,Xh,Wh,H0,nullptr,bh,Hc, mt*64,nt*64,BN,DH,DI,DI,DI,DH);
        else
            gemm_tile<false,true,3>(&sm,Xm,Wm,M0,nullptr,bm,Mc, mt*64,nt*64,BN,DH,DI,DI,DI,DH);
    }
    grid.sync();

    for(int it=0;it<10;it++){
        // ---- P1: T1 = Hc @ V ----
        for(int task=blockIdx.x;task<512;task+=GB){
            int mt=task>>1, nt=task&1;
            gemm_tile<false,false,0>(&sm,Hc,V,T1,nullptr,nullptr,nullptr,
                mt*64,nt*64,BN,DH,DH,DH,DH,DH);
        }
        grid.sync();
        // ---- P2: S = T1 @ Mc^T (batched) ----
        for(int task=blockIdx.x;task<2048;task+=GB){
            int b=task>>6, s2=task&63, mt=s2>>3, nt=s2&7;
            gemm_tile<false,true,0>(&sm,T1+(long)b*NHS,Mc+(long)b*NHS,S+(long)b*SMAT,
                nullptr,nullptr,nullptr, mt*64,nt*64,NT,NT,DH,DH,DH,NT);
        }
        grid.sync();
        // ---- P3: per-batch max partials ----
        for(int task=blockIdx.x;task<256;task+=GB){
            int b=task>>3, sl=task&7;
            int L=len[b];
            const float* Sb=S+(long)b*SMAT;
            float mx=-1e30f;
            for(int r=sl*64;r<sl*64+64;r++){
                if(r>L) break;
                for(int m=t+1;m<=L;m+=256)
                    if(m!=r) mx=fmaxf(mx,Sb[(long)r*NT+m]);
            }
            sm.red[t]=mx; __syncthreads();
            for(int s=128;s>0;s>>=1){ if(t<s) sm.red[t]=fmaxf(sm.red[t],sm.red[t+s]); __syncthreads(); }
            if(t==0) g_pm[b*8+sl]=sm.red[0];
            __syncthreads();
        }
        grid.sync();
        // ---- P4: c, colsum, buildL ----
        for(int task=blockIdx.x;task<BB;task+=GB){
            int b=task, L=len[b];
            float c=-1e30f;
            for(int k2=0;k2<8;k2++) c=fmaxf(c,g_pm[b*8+k2]);
            if(t==0) g_c[b]=c;
            const float* Sb=S+(long)b*SMAT;
            float* Lb=Lm+(long)b*SMAT;
            int j0=t, j1=t+256;
            int mA=j0+1, mB=j1+1;
            float cs0=0.f, cs1=0.f;
            for(int h=0;h<=L;h++){
                if(mA<=L && h!=mA) cs0+=expf(Sb[(long)h*NT+mA]-c);
                if(mB<NT && mB<=L && h!=mB) cs1+=expf(Sb[(long)h*NT+mB]-c);
            }
            auto lval=[&](int i,int j,int m,float cs)->float{
                if(i==NT-1) return (j==NT-1)?1.f:0.f;
                if(j==NT-1) return 0.f;
                float pad=(m>L)?1.f:0.f;
                if(i==0){
                    float a=(m<=L)?expf(Sb[m]-c):0.f;
                    return a+((j==0)?pad:0.f);
                }
                if(i==j) return cs+pad;
                int h=i+1;
                return (h<=L&&m<=L)? -expf(Sb[(long)h*NT+m]-c) : 0.f;
            };
            for(int i=0;i<NT;i++){
                Lb[(long)i*NT+j0]=lval(i,j0,mA,cs0);
                Lb[(long)i*NT+j1]=lval(i,j1,mB,cs1);
            }
        }
        grid.sync();
        // ---- P5: blocked LU ----
        for(int k=0;k<16;k++){
            int k0=k*32, rem=NT-k0-32;
            for(int task=blockIdx.x;task<128;task+=GB){
                int b=task>>2, role=task&3;
                float* Lb=Lm+(long)b*SMAT;
                float (*D)[33]=sm.s.T4[0];
                for(int i=t;i<1024;i+=256) D[i>>5][i&31]=Lb[(long)(k0+(i>>5))*NT+k0+(i&31)];
                __syncthreads();
                if(t<32){
                    for(int j=0;j<32;j++){
                        float inv=1.f/D[j][j];
                        if(t>j){
                            float l=D[t][j]*inv;
                            D[t][j]=l;
                            for(int jj=j+1;jj<32;jj++) D[t][jj]-=l*D[j][jj];
                        }
                        __syncwarp();
                    }
                }
                __syncthreads();
                if(role==0){
                    for(int i=t;i<1024;i+=256) Lb[(long)(k0+(i>>5))*NT+k0+(i&31)]=D[i>>5][i&31];
                    if(t==0){
                        float s=0.f;
                        for(int j=0;j<32;j++) s+=logf(fabsf(D[j][j]));
                        g_ldp[b*16+k]=s;
                    }
                }
                if(role<2){
                    int row=k0+32+role*256+t;
                    if(row<NT){
                        float x[32];
                        #pragma unroll
                        for(int j=0;j<32;j++) x[j]=Lb[(long)row*NT+k0+j];
                        #pragma unroll
                        for(int j=0;j<32;j++){
                            float xj=x[j];
                            #pragma unroll
                            for(int l=0;l<32;l++) if(l<j) xj-=x[l]*D[l][j];
                            x[j]=xj/D[j][j];
                        }
                        #pragma unroll
                        for(int j=0;j<32;j++) Lb[(long)row*NT+k0+j]=x[j];
                    }
                } else {
                    int cc=k0+32+(role-2)*256+t;
                    if(cc<NT){
                        float x[32];
                        #pragma unroll
                        for(int i=0;i<32;i++) x[i]=Lb[(long)(k0+i)*NT+cc];
                        #pragma unroll
                        for(int i=1;i<32;i++){
                            float xi=x[i];
                            #pragma unroll
                            for(int j=0;j<32;j++) if(j<i) xi-=D[i][j]*x[j];
                            x[i]=xi;
                        }
                        #pragma unroll
                        for(int i=0;i<32;i++) Lb[(long)(k0+i)*NT+cc]=x[i];
                    }
                }
                __syncthreads();
            }
            grid.sync();
            int nb=(rem+63)>>6;
            int ntasks=BB*nb*nb;
            for(int task=blockIdx.x;task<ntasks;task+=GB){
                int b=task/(nb*nb), s2=task%(nb*nb), mt=s2/nb, nt2=s2%nb;
                float* Lb=Lm+(long)b*SMAT;
                gemm_tile<false,false,1>(&sm, Lb+(long)(k0+32)*NT+k0, Lb+(long)k0*NT+(k0+32),
                    Lb+(long)(k0+32)*NT+(k0+32), nullptr,nullptr,nullptr,
                    mt*64,nt2*64,rem,rem,32,NT,NT,NT);
            }
            grid.sync();
        }
        // ---- P6: forward solve L Z = I (64-col stripes, 4-way kb parallel) ----
        for(int task=blockIdx.x;task<256;task+=GB){
            int b=task>>3, sI=task&7;
            const float* Lb=Lm+(long)b*SMAT;
            float* Zb=Li+(long)b*SMAT;
            int lc=t&63, grp=t>>6;
            int col=sI*64+lc;
            int start=2*sI;
            for(int ib=start;ib<16;ib++){
                float acc[32];
                #pragma unroll
                for(int r=0;r<32;r++) acc[r]=(grp==0 && ib*32+r==col)?1.f:0.f;
                int nkb=ib-start;
                for(int j0=0;j0<nkb;j0+=4){
                    int kb=start+j0+grp;
                    bool act=(kb<ib);
                    if(act){
                        for(int e=lc;e<1024;e+=64)
                            sm.s.T4[grp][e>>5][e&31]=Lb[(long)(ib*32+(e>>5))*NT + kb*32+(e&31)];
                    }
                    __syncthreads();
                    if(act){
                        #pragma unroll 4
                        for(int q=0;q<32;q++){
                            float xq=Zb[(long)(kb*32+q)*NT+col];
                            #pragma unroll
                            for(int r=0;r<32;r++) acc[r]-=sm.s.T4[grp][r][q]*xq;
                        }
                    }
                    __syncthreads();
                }
                if(grp>0){
                    #pragma unroll
                    for(int r=0;r<32;r++) sm.s.R[grp-1][r][lc]=acc[r];
                } else {
                    for(int e=lc;e<1024;e+=64)
                        sm.s.T4[0][e>>5][e&31]=Lb[(long)(ib*32+(e>>5))*NT + ib*32+(e&31)];
                }
                __syncthreads();
                if(grp==0){
                    #pragma unroll
                    for(int r=0;r<32;r++)
                        acc[r]+=sm.s.R[0][r][lc]+sm.s.R[1][r][lc]+sm.s.R[2][r][lc];
                    #pragma unroll
                    for(int r=1;r<32;r++){
                        float a=acc[r];
                        #pragma unroll
                        for(int q=0;q<32;q++) if(q<r) a-=sm.s.T4[0][r][q]*acc[q];
                        acc[r]=a;
                    }
                    #pragma unroll
                    for(int r=0;r<32;r++) Zb[(long)(ib*32+r)*NT+col]=acc[r];
                }
                __syncthreads();
            }
        }
        grid.sync();
        // ---- P7: backward solve U X = Z ----
        for(int task=blockIdx.x;task<256;task+=GB){
            int b=task>>3, sI=task&7;
            const float* Lb=Lm+(long)b*SMAT;
            float* Zb=Li+(long)b*SMAT;
            int lc=t&63, grp=t>>6;
            int col=sI*64+lc;
            int start=2*sI;
            for(int ib=15;ib>=0;ib--){
                float acc[32];
                if(grp==0 && ib>=start){
                    #pragma unroll
                    for(int r=0;r<32;r++) acc[r]=Zb[(long)(ib*32+r)*NT+col];
                } else {
                    #pragma unroll
                    for(int r=0;r<32;r++) acc[r]=0.f;
                }
                int nkb=15-ib;
                for(int j0=0;j0<nkb;j0+=4){
                    int kb=ib+1+j0+grp;
                    bool act=(kb<16);
                    if(act){
                        for(int e=lc;e<1024;e+=64)
                            sm.s.T4[grp][e>>5][e&31]=Lb[(long)(ib*32+(e>>5))*NT + kb*32+(e&31)];
                    }
                    __syncthreads();
                    if(act){
                        #pragma unroll 4
                        for(int q=0;q<32;q++){
                            float xq=Zb[(long)(kb*32+q)*NT+col];
                            #pragma unroll
                            for(int r=0;r<32;r++) acc[r]-=sm.s.T4[grp][r][q]*xq;
                        }
                    }
                    __syncthreads();
                }
                if(grp>0){
                    #pragma unroll
                    for(int r=0;r<32;r++) sm.s.R[grp-1][r][lc]=acc[r];
                } else {
                    for(int e=lc;e<1024;e+=64)
                        sm.s.T4[0][e>>5][e&31]=Lb[(long)(ib*32+(e>>5))*NT + ib*32+(e&31)];
                }
                __syncthreads();
                if(grp==0){
                    #pragma unroll
                    for(int r=0;r<32;r++)
                        acc[r]+=sm.s.R[0][r][lc]+sm.s.R[1][r][lc]+sm.s.R[2][r][lc];
                    #pragma unroll
                    for(int r=31;r>=0;r--){
                        float a=acc[r];
                        #pragma unroll
                        for(int q=0;q<32;q++) if(q>r) a-=sm.s.T4[0][r][q]*acc[q];
                        acc[r]=a/sm.s.T4[0][r][r];
                    }
                    #pragma unroll
                    for(int r=0;r<32;r++) Zb[(long)(ib*32+r)*NT+col]=acc[r];
                }
                __syncthreads();
            }
        }
        grid.sync();
        // ---- P8: marginals Y + entropy partials ----
        for(int task=blockIdx.x;task<8192;task+=GB){
            int b=task>>8, s2=task&255, hy=s2>>4, mxt=s2&15;
            int m0=mxt*32, h0=hy*32;
            const float* Lb=Li+(long)b*SMAT;
            const float* Sb=S+(long)b*SMAT;
            float* Yb=Y+(long)b*SMAT;
            int L=len[b]; float cb=g_c[b];
            for(int i=t;i<1024;i+=256){
                int mi=i>>5, hi=i&31;
                int m=m0+mi, h=h0+hi;
                sm.y.Lt[mi][hi]=(m>=1&&h>=1)? Lb[(long)(m-1)*NT+(h-1)] : 0.f;
            }
            if(t<32){
                int m=m0+t;
                sm.y.dg[t]=(m>=2)? Lb[(long)(m-1)*NT+(m-1)] : 0.f;
                sm.y.l0[t]=(m>=1)? Lb[(long)(m-1)*NT] : 0.f;
            }
            __syncthreads();
            float yts=0.f;
            int mi=t&31, hb2=t>>5;
            int m=m0+mi;
            #pragma unroll
            for(int p=0;p<4;p++){
                int hi=hb2+p*8;
                int h=h0+hi;
                float y=0.f;
                float sv=Sb[(long)h*NT+m];
                if(m>=1&&m<=L&&h<=L&&h!=m){
                    float a=expf(sv-cb);
                    float val=(h==0)? (sm.y.l0[mi]+sm.y.dg[mi])
                                    : (sm.y.dg[mi]-((h>=2)? sm.y.Lt[mi][hi]:0.f));
                    y=a*val; yts+=y*sv;
                }
                Yb[(long)h*NT+m]=y;
            }
            sm.y.red[t]=yts; __syncthreads();
            for(int s=128;s>0;s>>=1){ if(t<s) sm.y.red[t]+=sm.y.red[t+s]; __syncthreads(); }
            if(t==0) g_part[(long)b*256+hy*16+mxt]=sm.y.red[0];
            __syncthreads();
        }
        grid.sync();
        // ---- P9 (finalize) + P10 (feature GEMMs) fused ----
        int np=(it<9)? 1056 : 32;
        for(int task=blockIdx.x;task<np;task+=GB){
            if(task<32){
                int b=task;
                sm.red[t]=g_part[(long)b*256+t];
                __syncthreads();
                for(int s=128;s>0;s>>=1){ if(t<s) sm.red[t]+=sm.red[t+s]; __syncthreads(); }
                if(t==0){
                    float ld=0.f;
                    for(int kk=0;kk<16;kk++) ld+=g_ldp[b*16+kk];
                    float lz=ld+(float)len[b]*g_c[b];
                    logZ[b]=lz; entr[b]=lz-sm.red[0];
                }
                __syncthreads();
            } else {
                int t2=task-32;
                int which=t2>>9, sub=t2&511;
                int b=sub>>4, s3=sub&15, mt=s3>>1, nt2=s3&1;
                if(which==0)
                    gemm_tile<false,false,0>(&sm,Y+(long)b*SMAT,Mc+(long)b*NHS,T1+(long)b*NHS,
                        nullptr,nullptr,nullptr, mt*64,nt2*64,NT,DH,NT,NT,DH,DH);
                else
                    gemm_tile<true,false,0>(&sm,Y+(long)b*SMAT,Hc+(long)b*NHS,T2+(long)b*NHS,
                        nullptr,nullptr,nullptr, mt*64,nt2*64,NT,DH,NT,NT,DH,DH);
            }
        }
        grid.sync();
        // ---- P11: Hx = relu(H0 + T1@V^T), Mx = relu(M0 + T2@V) ----
        if(it<9){
            for(int task=blockIdx.x;task<1024;task+=GB){
                int which=task>>9, sub=task&511, mt=sub>>1, nt2=sub&1;
                if(which==0)
                    gemm_tile<false,true,2>(&sm,T1,V,Hx,H0,nullptr,nullptr,
                        mt*64,nt2*64,BN,DH,DH,DH,DH,DH);
                else
                    gemm_tile<false,false,2>(&sm,T2,V,Mx,M0,nullptr,nullptr,
                        mt*64,nt2*64,BN,DH,DH,DH,DH,DH);
            }
            grid.sync();
            float* tmp;
            tmp=Hc;Hc=Hx;Hx=tmp;
            tmp=Mc;Mc=Mx;Mx=tmp;
        }
    }
}

// ---------------- host launch ----------------
extern "C" void kernel_launch(void* const* d_in, const int* in_sizes, int n_in,
                              void* d_out, int out_size){
    const float* Xh=(const float*)d_in[0];
    const float* Xm=(const float*)d_in[1];
    const int*   len=(const int*)d_in[2];
    const float* Wh=(const float*)d_in[3];
    const float* bh=(const float*)d_in[4];
    const float* Wm=(const float*)d_in[5];
    const float* bm=(const float*)d_in[6];
    const float* V =(const float*)d_in[7];
    float* out=(float*)d_out;
    float* S   =out;
    float* logZ=out+(long)BB*SMAT;
    float* Y   =logZ+BB;
    float* entr=Y+(long)BB*SMAT;

    int dev=0; cudaGetDevice(&dev);
    int sms=0; cudaDeviceGetAttribute(&sms,cudaDevAttrMultiProcessorCount,dev);
    int occ=0; cudaOccupancyMaxActiveBlocksPerMultiprocessor(&occ,mega_k,256,0);
    if(occ<1) occ=1;
    int nblk=sms*occ;

    void* args[]={(void*)&Xh,(void*)&Xm,(void*)&len,(void*)&Wh,(void*)&bh,
                  (void*)&Wm,(void*)&bm,(void*)&V,
                  (void*)&S,(void*)&logZ,(void*)&Y,(void*)&entr};
    cudaLaunchCooperativeKernel((const void*)mega_k,dim3(nblk),dim3(256),args,0,(cudaStream_t)0);
}

// round 9
// speedup vs baseline: 1.7488x; 1.2450x over previous
#include <cuda_runtime.h>
#include <cooperative_groups.h>
#include <math.h>
namespace cg = cooperative_groups;

#define BB 32
#define NT 512
#define DH 128
#define DI 256
#define BN (BB*NT)
#define SMAT (NT*NT)
#define NHS ((long)NT*DH)

// ---------------- static device scratch ----------------
__device__ float g_H0[BN*DH];
__device__ float g_M0[BN*DH];
__device__ float g_Ha[BN*DH];
__device__ float g_Hb[BN*DH];
__device__ float g_Ma[BN*DH];
__device__ float g_Mb[BN*DH];
__device__ float g_T1[BN*DH];
__device__ float g_T2[BN*DH];
__device__ float g_Lm[(long)BB*SMAT];
__device__ float g_Li[(long)BB*SMAT];
__device__ float g_cs[BB*NT];
__device__ float g_c[BB];
__device__ float g_pm[BB*8];
__device__ float g_ldp[BB*16];
__device__ float g_part[BB*256];

// ---------------- shared memory union ----------------
struct SG { float As[2][16][132]; float Bs[2][16][68]; };
struct SI { float T4[4][32][33]; float R[3][32][65]; };
struct SY { float Lt[32][33]; float dg[32]; float l0[32]; float red[256]; };
union USm { SG g; SI s; SY y; float red[256]; };

// ---------------- 128x64x16 GEMM tile, double-buffered, float4, 256 thr ----------------
// thread (ty=t>>4, tx=t&15) owns rows m0+ty*8..+7, cols n0+tx*4..+3
// EPI: 0 C=acc | 1 C-=acc | 2 C=relu(C0+acc) | 3 C=acc+bias, C2=relu(C)
template<bool TRA,bool TRB,int EPI>
__device__ __forceinline__ void gemm_tile(USm* sm,
    const float* __restrict__ A,const float* __restrict__ B,
    float* __restrict__ C,const float* __restrict__ C0,
    const float* __restrict__ bias,float* __restrict__ C2,
    int m0,int n0,int M,int N,int K,int lda,int ldb,int ldc)
{
    const int t=threadIdx.x;
    const int ty=t>>4, tx=t&15;
    float acc[8][4];
    #pragma unroll
    for(int i=0;i<8;i++)
        #pragma unroll
        for(int j=0;j<4;j++) acc[i][j]=0.f;

    const float4 z4=make_float4(0.f,0.f,0.f,0.f);
    auto ldA=[&](int kp,float4& v0,float4& v1){
        if(!TRA){
            int row=t>>1, kq=t&1;
            if(m0+row<M){
                const float* p=&A[(long)(m0+row)*lda + kp+kq*8];
                v0=*reinterpret_cast<const float4*>(p);
                v1=*reinterpret_cast<const float4*>(p+4);
            } else { v0=z4; v1=z4; }
        } else {
            int mq=t&31, kk=t>>5;
            int m=m0+mq*4;
            if(m<M){
                v0=*reinterpret_cast<const float4*>(&A[(long)(kp+kk)*lda + m]);
                v1=*reinterpret_cast<const float4*>(&A[(long)(kp+kk+8)*lda + m]);
            } else { v0=z4; v1=z4; }
        }
    };
    auto stA=[&](int buf,float4 v0,float4 v1){
        if(!TRA){
            int row=t>>1, kq=t&1;
            sm->g.As[buf][kq*8+0][row]=v0.x; sm->g.As[buf][kq*8+1][row]=v0.y;
            sm->g.As[buf][kq*8+2][row]=v0.z; sm->g.As[buf][kq*8+3][row]=v0.w;
            sm->g.As[buf][kq*8+4][row]=v1.x; sm->g.As[buf][kq*8+5][row]=v1.y;
            sm->g.As[buf][kq*8+6][row]=v1.z; sm->g.As[buf][kq*8+7][row]=v1.w;
        } else {
            int mq=t&31, kk=t>>5;
            *reinterpret_cast<float4*>(&sm->g.As[buf][kk][mq*4])=v0;
            *reinterpret_cast<float4*>(&sm->g.As[buf][kk+8][mq*4])=v1;
        }
    };
    auto ldB=[&](int kp)->float4{
        if(!TRB){
            int kk=t>>4, nq=t&15;
            if(n0+nq*4<N) return *reinterpret_cast<const float4*>(&B[(long)(kp+kk)*ldb + n0+nq*4]);
            return z4;
        } else {
            int row=t>>2, kq=t&3;
            if(n0+row<N) return *reinterpret_cast<const float4*>(&B[(long)(n0+row)*ldb + kp+kq*4]);
            return z4;
        }
    };
    auto stB=[&](int buf,float4 v){
        if(!TRB){
            int kk=t>>4, nq=t&15;
            *reinterpret_cast<float4*>(&sm->g.Bs[buf][kk][nq*4])=v;
        } else {
            int row=t>>2, kq=t&3;
            sm->g.Bs[buf][kq*4+0][row]=v.x; sm->g.Bs[buf][kq*4+1][row]=v.y;
            sm->g.Bs[buf][kq*4+2][row]=v.z; sm->g.Bs[buf][kq*4+3][row]=v.w;
        }
    };

    const int nk=K>>4;
    {
        float4 a0,a1; ldA(0,a0,a1);
        float4 b0=ldB(0);
        stA(0,a0,a1); stB(0,b0);
    }
    __syncthreads();
    for(int kb=0;kb<nk;kb++){
        int cur=kb&1;
        float4 pa0,pa1,pb;
        bool more=(kb+1<nk);
        if(more){ ldA((kb+1)<<4,pa0,pa1); pb=ldB((kb+1)<<4); }
        #pragma unroll
        for(int kk=0;kk<16;kk++){
            float4 a0=*reinterpret_cast<const float4*>(&sm->g.As[cur][kk][ty*8]);
            float4 a1=*reinterpret_cast<const float4*>(&sm->g.As[cur][kk][ty*8+4]);
            float4 b0=*reinterpret_cast<const float4*>(&sm->g.Bs[cur][kk][tx*4]);
            float a[8]={a0.x,a0.y,a0.z,a0.w,a1.x,a1.y,a1.z,a1.w};
            float b[4]={b0.x,b0.y,b0.z,b0.w};
            #pragma unroll
            for(int i=0;i<8;i++)
                #pragma unroll
                for(int j=0;j<4;j++) acc[i][j]=fmaf(a[i],b[j],acc[i][j]);
        }
        if(more){ stA(cur^1,pa0,pa1); stB(cur^1,pb); }
        __syncthreads();
    }
    int n=n0+tx*4;
    if(n<N){
        #pragma unroll
        for(int i=0;i<8;i++){
            int m=m0+ty*8+i;
            if(m<M){
                long off=(long)m*ldc+n;
                float4 v=make_float4(acc[i][0],acc[i][1],acc[i][2],acc[i][3]);
                if(EPI==0) *reinterpret_cast<float4*>(&C[off])=v;
                else if(EPI==1){
                    float4 c=*reinterpret_cast<const float4*>(&C[off]);
                    c.x-=v.x; c.y-=v.y; c.z-=v.z; c.w-=v.w;
                    *reinterpret_cast<float4*>(&C[off])=c;
                } else if(EPI==2){
                    float4 c=*reinterpret_cast<const float4*>(&C0[off]);
                    c.x=fmaxf(c.x+v.x,0.f); c.y=fmaxf(c.y+v.y,0.f);
                    c.z=fmaxf(c.z+v.z,0.f); c.w=fmaxf(c.w+v.w,0.f);
                    *reinterpret_cast<float4*>(&C[off])=c;
                } else {
                    float4 bb=*reinterpret_cast<const float4*>(&bias[n]);
                    v.x+=bb.x; v.y+=bb.y; v.z+=bb.z; v.w+=bb.w;
                    *reinterpret_cast<float4*>(&C[off])=v;
                    float4 r=make_float4(fmaxf(v.x,0.f),fmaxf(v.y,0.f),fmaxf(v.z,0.f),fmaxf(v.w,0.f));
                    *reinterpret_cast<float4*>(&C2[off])=r;
                }
            }
        }
    }
}

// ---------------- the mega kernel ----------------
__global__ void __launch_bounds__(256,2) mega_k(
    const float* __restrict__ Xh,const float* __restrict__ Xm,
    const int* __restrict__ len,
    const float* __restrict__ Wh,const float* __restrict__ bh,
    const float* __restrict__ Wm,const float* __restrict__ bm,
    const float* __restrict__ V,
    float* __restrict__ S,float* __restrict__ logZ,
    float* __restrict__ Y,float* __restrict__ entr)
{
    cg::grid_group grid=cg::this_grid();
    __shared__ USm sm;
    const int t=threadIdx.x;
    const int GB=gridDim.x;

    float *H0=g_H0,*M0=g_M0,*T1=g_T1,*T2=g_T2,*Lm=g_Lm,*Li=g_Li;
    float *Hc=g_Ha,*Mc=g_Ma,*Hx=g_Hb,*Mx=g_Mb;

    // ---- P0: H0 = Xh@Wh^T+bh (Ha=relu), M0 likewise ----
    for(int task=blockIdx.x;task<512;task+=GB){
        int which=task>>8, sub=task&255, mt=sub>>1, nt=sub&1;
        if(which==0)
            gemm_tile<false,true,3>(&sm,Xh,Wh,H0,nullptr,bh,Hc, mt*128,nt*64,BN,DH,DI,DI,DI,DH);
        else
            gemm_tile<false,true,3>(&sm,Xm,Wm,M0,nullptr,bm,Mc, mt*128,nt*64,BN,DH,DI,DI,DI,DH);
    }
    grid.sync();

    for(int it=0;it<10;it++){
        // ---- P1: T1 = Hc @ V ----
        for(int task=blockIdx.x;task<256;task+=GB){
            int mt=task>>1, nt=task&1;
            gemm_tile<false,false,0>(&sm,Hc,V,T1,nullptr,nullptr,nullptr,
                mt*128,nt*64,BN,DH,DH,DH,DH,DH);
        }
        grid.sync();
        // ---- P2: S = T1 @ Mc^T (batched) ----
        for(int task=blockIdx.x;task<1024;task+=GB){
            int b=task>>5, s2=task&31, mt=s2>>3, nt=s2&7;
            gemm_tile<false,true,0>(&sm,T1+(long)b*NHS,Mc+(long)b*NHS,S+(long)b*SMAT,
                nullptr,nullptr,nullptr, mt*128,nt*64,NT,NT,DH,DH,DH,NT);
        }
        grid.sync();
        // ---- P3: per-batch max partials ----
        for(int task=blockIdx.x;task<256;task+=GB){
            int b=task>>3, sl=task&7;
            int L=len[b];
            const float* Sb=S+(long)b*SMAT;
            float mx=-1e30f;
            for(int r=sl*64;r<sl*64+64;r++){
                if(r>L) break;
                for(int m=t+1;m<=L;m+=256)
                    if(m!=r) mx=fmaxf(mx,Sb[(long)r*NT+m]);
            }
            sm.red[t]=mx; __syncthreads();
            for(int s=128;s>0;s>>=1){ if(t<s) sm.red[t]=fmaxf(sm.red[t],sm.red[t+s]); __syncthreads(); }
            if(t==0) g_pm[b*8+sl]=sm.red[0];
            __syncthreads();
        }
        grid.sync();
        // ---- P4a: c + column sums ----
        for(int task=blockIdx.x;task<64;task+=GB){
            int b=task>>1, half=task&1;
            int L=len[b];
            float c=-1e30f;
            for(int k2=0;k2<8;k2++) c=fmaxf(c,g_pm[b*8+k2]);
            if(half==0 && t==0) g_c[b]=c;
            int m=half*256+t;
            const float* Sb=S+(long)b*SMAT;
            float s=0.f;
            if(m>=1 && m<=L){
                for(int h=0;h<=L;h++)
                    if(h!=m) s+=expf(Sb[(long)h*NT+m]-c);
            }
            g_cs[b*NT+m]=s;
        }
        grid.sync();
        // ---- P4b: build Lhat (row chunks) ----
        for(int task=blockIdx.x;task<256;task+=GB){
            int b=task>>3, rc=task&7;
            int L=len[b]; float c=g_c[b];
            const float* Sb=S+(long)b*SMAT;
            float* Lb=Lm+(long)b*SMAT;
            for(int i=rc*64;i<rc*64+64;i++){
                #pragma unroll
                for(int w=0;w<2;w++){
                    int j=t+w*256;
                    int m=j+1;
                    float v;
                    if(i==NT-1) v=(j==NT-1)?1.f:0.f;
                    else if(j==NT-1) v=0.f;
                    else {
                        float pad=(m>L)?1.f:0.f;
                        if(i==0){
                            float a=(m<=L)?expf(Sb[m]-c):0.f;
                            v=a+((j==0)?pad:0.f);
                        } else if(i==j){
                            v=g_cs[b*NT+m]+pad;
                        } else {
                            int h=i+1;
                            v=(h<=L&&m<=L)? -expf(Sb[(long)h*NT+m]-c) : 0.f;
                        }
                    }
                    Lb[(long)i*NT+j]=v;
                }
            }
        }
        grid.sync();
        // ---- P5: blocked LU ----
        for(int k=0;k<16;k++){
            int k0=k*32, rem=NT-k0-32;
            for(int task=blockIdx.x;task<128;task+=GB){
                int b=task>>2, role=task&3;
                float* Lb=Lm+(long)b*SMAT;
                float (*D)[33]=sm.s.T4[0];
                for(int i=t;i<1024;i+=256) D[i>>5][i&31]=Lb[(long)(k0+(i>>5))*NT+k0+(i&31)];
                __syncthreads();
                if(t<32){
                    for(int j=0;j<32;j++){
                        float inv=1.f/D[j][j];
                        if(t>j){
                            float l=D[t][j]*inv;
                            D[t][j]=l;
                            for(int jj=j+1;jj<32;jj++) D[t][jj]-=l*D[j][jj];
                        }
                        __syncwarp();
                    }
                }
                __syncthreads();
                if(role==0){
                    for(int i=t;i<1024;i+=256) Lb[(long)(k0+(i>>5))*NT+k0+(i&31)]=D[i>>5][i&31];
                    if(t==0){
                        float s=0.f;
                        for(int j=0;j<32;j++) s+=logf(fabsf(D[j][j]));
                        g_ldp[b*16+k]=s;
                    }
                }
                if(role<2){
                    int row=k0+32+role*256+t;
                    if(row<NT){
                        float x[32];
                        #pragma unroll
                        for(int j=0;j<32;j++) x[j]=Lb[(long)row*NT+k0+j];
                        #pragma unroll
                        for(int j=0;j<32;j++){
                            float xj=x[j];
                            #pragma unroll
                            for(int l=0;l<32;l++) if(l<j) xj-=x[l]*D[l][j];
                            x[j]=xj/D[j][j];
                        }
                        #pragma unroll
                        for(int j=0;j<32;j++) Lb[(long)row*NT+k0+j]=x[j];
                    }
                } else {
                    int cc=k0+32+(role-2)*256+t;
                    if(cc<NT){
                        float x[32];
                        #pragma unroll
                        for(int i=0;i<32;i++) x[i]=Lb[(long)(k0+i)*NT+cc];
                        #pragma unroll
                        for(int i=1;i<32;i++){
                            float xi=x[i];
                            #pragma unroll
                            for(int j=0;j<32;j++) if(j<i) xi-=D[i][j]*x[j];
                            x[i]=xi;
                        }
                        #pragma unroll
                        for(int i=0;i<32;i++) Lb[(long)(k0+i)*NT+cc]=x[i];
                    }
                }
                __syncthreads();
            }
            grid.sync();
            int nbM=(rem+127)>>7, nbN=(rem+63)>>6;
            int ntasks=BB*nbM*nbN;
            for(int task=blockIdx.x;task<ntasks;task+=GB){
                int b=task/(nbM*nbN), s2=task%(nbM*nbN), mt=s2/nbN, nt2=s2%nbN;
                float* Lb=Lm+(long)b*SMAT;
                gemm_tile<false,false,1>(&sm, Lb+(long)(k0+32)*NT+k0, Lb+(long)k0*NT+(k0+32),
                    Lb+(long)(k0+32)*NT+(k0+32), nullptr,nullptr,nullptr,
                    mt*128,nt2*64,rem,rem,32,NT,NT,NT);
            }
            grid.sync();
        }
        // ---- P6: forward solve L Z = I (64-col stripes, 4-way kb parallel) ----
        for(int task=blockIdx.x;task<256;task+=GB){
            int b=task>>3, sI=task&7;
            const float* Lb=Lm+(long)b*SMAT;
            float* Zb=Li+(long)b*SMAT;
            int lc=t&63, grp=t>>6;
            int col=sI*64+lc;
            int start=2*sI;
            for(int ib=start;ib<16;ib++){
                float acc[32];
                #pragma unroll
                for(int r=0;r<32;r++) acc[r]=(grp==0 && ib*32+r==col)?1.f:0.f;
                int nkb=ib-start;
                for(int j0=0;j0<nkb;j0+=4){
                    int kb=start+j0+grp;
                    bool act=(kb<ib);
                    if(act){
                        for(int e=lc;e<1024;e+=64)
                            sm.s.T4[grp][e>>5][e&31]=Lb[(long)(ib*32+(e>>5))*NT + kb*32+(e&31)];
                    }
                    __syncthreads();
                    if(act){
                        #pragma unroll 4
                        for(int q=0;q<32;q++){
                            float xq=Zb[(long)(kb*32+q)*NT+col];
                            #pragma unroll
                            for(int r=0;r<32;r++) acc[r]-=sm.s.T4[grp][r][q]*xq;
                        }
                    }
                    __syncthreads();
                }
                if(grp>0){
                    #pragma unroll
                    for(int r=0;r<32;r++) sm.s.R[grp-1][r][lc]=acc[r];
                } else {
                    for(int e=lc;e<1024;e+=64)
                        sm.s.T4[0][e>>5][e&31]=Lb[(long)(ib*32+(e>>5))*NT + ib*32+(e&31)];
                }
                __syncthreads();
                if(grp==0){
                    #pragma unroll
                    for(int r=0;r<32;r++)
                        acc[r]+=sm.s.R[0][r][lc]+sm.s.R[1][r][lc]+sm.s.R[2][r][lc];
                    #pragma unroll
                    for(int r=1;r<32;r++){
                        float a=acc[r];
                        #pragma unroll
                        for(int q=0;q<32;q++) if(q<r) a-=sm.s.T4[0][r][q]*acc[q];
                        acc[r]=a;
                    }
                    #pragma unroll
                    for(int r=0;r<32;r++) Zb[(long)(ib*32+r)*NT+col]=acc[r];
                }
                __syncthreads();
            }
        }
        grid.sync();
        // ---- P7: backward solve U X = Z ----
        for(int task=blockIdx.x;task<256;task+=GB){
            int b=task>>3, sI=task&7;
            const float* Lb=Lm+(long)b*SMAT;
            float* Zb=Li+(long)b*SMAT;
            int lc=t&63, grp=t>>6;
            int col=sI*64+lc;
            int start=2*sI;
            for(int ib=15;ib>=0;ib--){
                float acc[32];
                if(grp==0 && ib>=start){
                    #pragma unroll
                    for(int r=0;r<32;r++) acc[r]=Zb[(long)(ib*32+r)*NT+col];
                } else {
                    #pragma unroll
                    for(int r=0;r<32;r++) acc[r]=0.f;
                }
                int nkb=15-ib;
                for(int j0=0;j0<nkb;j0+=4){
                    int kb=ib+1+j0+grp;
                    bool act=(kb<16);
                    if(act){
                        for(int e=lc;e<1024;e+=64)
                            sm.s.T4[grp][e>>5][e&31]=Lb[(long)(ib*32+(e>>5))*NT + kb*32+(e&31)];
                    }
                    __syncthreads();
                    if(act){
                        #pragma unroll 4
                        for(int q=0;q<32;q++){
                            float xq=Zb[(long)(kb*32+q)*NT+col];
                            #pragma unroll
                            for(int r=0;r<32;r++) acc[r]-=sm.s.T4[grp][r][q]*xq;
                        }
                    }
                    __syncthreads();
                }
                if(grp>0){
                    #pragma unroll
                    for(int r=0;r<32;r++) sm.s.R[grp-1][r][lc]=acc[r];
                } else {
                    for(int e=lc;e<1024;e+=64)
                        sm.s.T4[0][e>>5][e&31]=Lb[(long)(ib*32+(e>>5))*NT + ib*32+(e&31)];
                }
                __syncthreads();
                if(grp==0){
                    #pragma unroll
                    for(int r=0;r<32;r++)
                        acc[r]+=sm.s.R[0][r][lc]+sm.s.R[1][r][lc]+sm.s.R[2][r][lc];
                    #pragma unroll
                    for(int r=31;r>=0;r--){
                        float a=acc[r];
                        #pragma unroll
                        for(int q=0;q<32;q++) if(q>r) a-=sm.s.T4[0][r][q]*acc[q];
                        acc[r]=a/sm.s.T4[0][r][r];
                    }
                    #pragma unroll
                    for(int r=0;r<32;r++) Zb[(long)(ib*32+r)*NT+col]=acc[r];
                }
                __syncthreads();
            }
        }
        grid.sync();
        // ---- P8: marginals Y + entropy partials ----
        for(int task=blockIdx.x;task<8192;task+=GB){
            int b=task>>8, s2=task&255, hy=s2>>4, mxt=s2&15;
            int m0=mxt*32, h0=hy*32;
            const float* Lb=Li+(long)b*SMAT;
            const float* Sb=S+(long)b*SMAT;
            float* Yb=Y+(long)b*SMAT;
            int L=len[b]; float cb=g_c[b];
            for(int i=t;i<1024;i+=256){
                int mi=i>>5, hi=i&31;
                int m=m0+mi, h=h0+hi;
                sm.y.Lt[mi][hi]=(m>=1&&h>=1)? Lb[(long)(m-1)*NT+(h-1)] : 0.f;
            }
            if(t<32){
                int m=m0+t;
                sm.y.dg[t]=(m>=2)? Lb[(long)(m-1)*NT+(m-1)] : 0.f;
                sm.y.l0[t]=(m>=1)? Lb[(long)(m-1)*NT] : 0.f;
            }
            __syncthreads();
            float yts=0.f;
            int mi=t&31, hb2=t>>5;
            int m=m0+mi;
            #pragma unroll
            for(int p=0;p<4;p++){
                int hi=hb2+p*8;
                int h=h0+hi;
                float y=0.f;
                float sv=Sb[(long)h*NT+m];
                if(m>=1&&m<=L&&h<=L&&h!=m){
                    float a=expf(sv-cb);
                    float val=(h==0)? (sm.y.l0[mi]+sm.y.dg[mi])
                                    : (sm.y.dg[mi]-((h>=2)? sm.y.Lt[mi][hi]:0.f));
                    y=a*val; yts+=y*sv;
                }
                Yb[(long)h*NT+m]=y;
            }
            sm.y.red[t]=yts; __syncthreads();
            for(int s=128;s>0;s>>=1){ if(t<s) sm.y.red[t]+=sm.y.red[t+s]; __syncthreads(); }
            if(t==0) g_part[(long)b*256+hy*16+mxt]=sm.y.red[0];
            __syncthreads();
        }
        grid.sync();
        // ---- P9 (finalize) + P10 (feature GEMMs) fused ----
        int np=(it<9)? 544 : 32;
        for(int task=blockIdx.x;task<np;task+=GB){
            if(task<32){
                int b=task;
                sm.red[t]=g_part[(long)b*256+t];
                __syncthreads();
                for(int s=128;s>0;s>>=1){ if(t<s) sm.red[t]+=sm.red[t+s]; __syncthreads(); }
                if(t==0){
                    float ld=0.f;
                    for(int kk=0;kk<16;kk++) ld+=g_ldp[b*16+kk];
                    float lz=ld+(float)len[b]*g_c[b];
                    logZ[b]=lz; entr[b]=lz-sm.red[0];
                }
                __syncthreads();
            } else {
                int t2=task-32;
                int which=t2>>8, sub=t2&255;
                int b=sub>>3, s3=sub&7, mt=s3>>1, nt2=s3&1;
                if(which==0)
                    gemm_tile<false,false,0>(&sm,Y+(long)b*SMAT,Mc+(long)b*NHS,T1+(long)b*NHS,
                        nullptr,nullptr,nullptr, mt*128,nt2*64,NT,DH,NT,NT,DH,DH);
                else
                    gemm_tile<true,false,0>(&sm,Y+(long)b*SMAT,Hc+(long)b*NHS,T2+(long)b*NHS,
                        nullptr,nullptr,nullptr, mt*128,nt2*64,NT,DH,NT,NT,DH,DH);
            }
        }
        grid.sync();
        // ---- P11: Hx = relu(H0 + T1@V^T), Mx = relu(M0 + T2@V) ----
        if(it<9){
            for(int task=blockIdx.x;task<512;task+=GB){
                int which=task>>8, sub=task&255, mt=sub>>1, nt2=sub&1;
                if(which==0)
                    gemm_tile<false,true,2>(&sm,T1,V,Hx,H0,nullptr,nullptr,
                        mt*128,nt2*64,BN,DH,DH,DH,DH,DH);
                else
                    gemm_tile<false,false,2>(&sm,T2,V,Mx,M0,nullptr,nullptr,
                        mt*128,nt2*64,BN,DH,DH,DH,DH,DH);
            }
            grid.sync();
            float* tmp;
            tmp=Hc;Hc=Hx;Hx=tmp;
            tmp=Mc;Mc=Mx;Mx=tmp;
        }
    }
}

// ---------------- host launch ----------------
extern "C" void kernel_launch(void* const* d_in, const int* in_sizes, int n_in,
                              void* d_out, int out_size){
    const float* Xh=(const float*)d_in[0];
    const float* Xm=(const float*)d_in[1];
    const int*   len=(const int*)d_in[2];
    const float* Wh=(const float*)d_in[3];
    const float* bh=(const float*)d_in[4];
    const float* Wm=(const float*)d_in[5];
    const float* bm=(const float*)d_in[6];
    const float* V =(const float*)d_in[7];
    float* out=(float*)d_out;
    float* S   =out;
    float* logZ=out+(long)BB*SMAT;
    float* Y   =logZ+BB;
    float* entr=Y+(long)BB*SMAT;

    int dev=0; cudaGetDevice(&dev);
    int sms=0; cudaDeviceGetAttribute(&sms,cudaDevAttrMultiProcessorCount,dev);
    int occ=0; cudaOccupancyMaxActiveBlocksPerMultiprocessor(&occ,mega_k,256,0);
    if(occ<1) occ=1;
    int nblk=sms*occ;

    void* args[]={(void*)&Xh,(void*)&Xm,(void*)&len,(void*)&Wh,(void*)&bh,
                  (void*)&Wm,(void*)&bm,(void*)&V,
                  (void*)&S,(void*)&logZ,(void*)&Y,(void*)&entr};
    cudaLaunchCooperativeKernel((const void*)mega_k,dim3(nblk),dim3(256),args,0,(cudaStream_t)0);
}

// round 11
// speedup vs baseline: 1.7913x; 1.0243x over previous
#include <cuda_runtime.h>
#include <cooperative_groups.h>
#include <math.h>
namespace cg = cooperative_groups;

#define BB 32
#define NT 512
#define DH 128
#define DI 256
#define BN (BB*NT)
#define SMAT (NT*NT)
#define NHS ((long)NT*DH)

// ---------------- static device scratch ----------------
__device__ float g_H0[BN*DH];
__device__ float g_M0[BN*DH];
__device__ float g_Ha[BN*DH];
__device__ float g_Hb[BN*DH];
__device__ float g_Ma[BN*DH];
__device__ float g_Mb[BN*DH];
__device__ float g_T1[BN*DH];
__device__ float g_T2[BN*DH];
__device__ float g_Lm[(long)BB*SMAT];
__device__ float g_Li[(long)BB*SMAT];
__device__ float g_cs[BB*NT];
__device__ float g_c[BB];
__device__ unsigned g_pmInt[BB];
__device__ float g_ldp[BB*8];
__device__ float g_part[BB*256];

// monotonic float<->uint encode for deterministic atomicMax
__device__ __forceinline__ unsigned fenc(float x){
    unsigned u=__float_as_uint(x);
    return (u&0x80000000u)? ~u : (u|0x80000000u);
}
__device__ __forceinline__ float fdec(unsigned u){
    unsigned b=(u&0x80000000u)? (u&0x7fffffffu) : ~u;
    return __uint_as_float(b);
}

// ---------------- shared memory union ----------------
struct SG { float As[2][16][132]; float Bs[2][16][68]; };
struct SI { float T4[4][32][33]; float R[3][32][65]; };
struct SD { float sd[64][65]; };
struct SY { float Lt[32][33]; float dg[32]; float l0[32]; float red[256]; };
union USm { SG g; SI s; SD d; SY y; float red[256]; };

// ---------------- 128x64xK GEMM tile, double-buffered, float4, 256 thr ----------------
// EPI: 0 C=acc | 1 C-=acc | 2 C=relu(C0+acc) | 3 C=acc+bias,C2=relu(C) | 4 C=acc + masked atomic max
template<bool TRA,bool TRB,int EPI>
__device__ __forceinline__ void gemm_tile(USm* sm,
    const float* __restrict__ A,const float* __restrict__ B,
    float* __restrict__ C,const float* __restrict__ C0,
    const float* __restrict__ bias,float* __restrict__ C2,
    int m0,int n0,int M,int N,int K,int lda,int ldb,int ldc,
    int Lv=0, unsigned* pmax=nullptr)
{
    const int t=threadIdx.x;
    const int ty=t>>4, tx=t&15;
    float acc[8][4];
    #pragma unroll
    for(int i=0;i<8;i++)
        #pragma unroll
        for(int j=0;j<4;j++) acc[i][j]=0.f;

    const float4 z4=make_float4(0.f,0.f,0.f,0.f);
    auto ldA=[&](int kp,float4& v0,float4& v1){
        if(!TRA){
            int row=t>>1, kq=t&1;
            if(m0+row<M){
                const float* p=&A[(long)(m0+row)*lda + kp+kq*8];
                v0=*reinterpret_cast<const float4*>(p);
                v1=*reinterpret_cast<const float4*>(p+4);
            } else { v0=z4; v1=z4; }
        } else {
            int mq=t&31, kk=t>>5;
            int m=m0+mq*4;
            if(m<M){
                v0=*reinterpret_cast<const float4*>(&A[(long)(kp+kk)*lda + m]);
                v1=*reinterpret_cast<const float4*>(&A[(long)(kp+kk+8)*lda + m]);
            } else { v0=z4; v1=z4; }
        }
    };
    auto stA=[&](int buf,float4 v0,float4 v1){
        if(!TRA){
            int row=t>>1, kq=t&1;
            sm->g.As[buf][kq*8+0][row]=v0.x; sm->g.As[buf][kq*8+1][row]=v0.y;
            sm->g.As[buf][kq*8+2][row]=v0.z; sm->g.As[buf][kq*8+3][row]=v0.w;
            sm->g.As[buf][kq*8+4][row]=v1.x; sm->g.As[buf][kq*8+5][row]=v1.y;
            sm->g.As[buf][kq*8+6][row]=v1.z; sm->g.As[buf][kq*8+7][row]=v1.w;
        } else {
            int mq=t&31, kk=t>>5;
            *reinterpret_cast<float4*>(&sm->g.As[buf][kk][mq*4])=v0;
            *reinterpret_cast<float4*>(&sm->g.As[buf][kk+8][mq*4])=v1;
        }
    };
    auto ldB=[&](int kp)->float4{
        if(!TRB){
            int kk=t>>4, nq=t&15;
            if(n0+nq*4<N) return *reinterpret_cast<const float4*>(&B[(long)(kp+kk)*ldb + n0+nq*4]);
            return z4;
        } else {
            int row=t>>2, kq=t&3;
            if(n0+row<N) return *reinterpret_cast<const float4*>(&B[(long)(n0+row)*ldb + kp+kq*4]);
            return z4;
        }
    };
    auto stB=[&](int buf,float4 v){
        if(!TRB){
            int kk=t>>4, nq=t&15;
            *reinterpret_cast<float4*>(&sm->g.Bs[buf][kk][nq*4])=v;
        } else {
            int row=t>>2, kq=t&3;
            sm->g.Bs[buf][kq*4+0][row]=v.x; sm->g.Bs[buf][kq*4+1][row]=v.y;
            sm->g.Bs[buf][kq*4+2][row]=v.z; sm->g.Bs[buf][kq*4+3][row]=v.w;
        }
    };

    const int nk=K>>4;
    {
        float4 a0,a1; ldA(0,a0,a1);
        float4 b0=ldB(0);
        stA(0,a0,a1); stB(0,b0);
    }
    __syncthreads();
    for(int kb=0;kb<nk;kb++){
        int cur=kb&1;
        float4 pa0,pa1,pb;
        bool more=(kb+1<nk);
        if(more){ ldA((kb+1)<<4,pa0,pa1); pb=ldB((kb+1)<<4); }
        #pragma unroll
        for(int kk=0;kk<16;kk++){
            float4 a0=*reinterpret_cast<const float4*>(&sm->g.As[cur][kk][ty*8]);
            float4 a1=*reinterpret_cast<const float4*>(&sm->g.As[cur][kk][ty*8+4]);
            float4 b0=*reinterpret_cast<const float4*>(&sm->g.Bs[cur][kk][tx*4]);
            float a[8]={a0.x,a0.y,a0.z,a0.w,a1.x,a1.y,a1.z,a1.w};
            float b[4]={b0.x,b0.y,b0.z,b0.w};
            #pragma unroll
            for(int i=0;i<8;i++)
                #pragma unroll
                for(int j=0;j<4;j++) acc[i][j]=fmaf(a[i],b[j],acc[i][j]);
        }
        if(more){ stA(cur^1,pa0,pa1); stB(cur^1,pb); }
        __syncthreads();
    }
    float mx=-1e30f;
    int n=n0+tx*4;
    if(n<N){
        #pragma unroll
        for(int i=0;i<8;i++){
            int m=m0+ty*8+i;
            if(m<M){
                long off=(long)m*ldc+n;
                float4 v=make_float4(acc[i][0],acc[i][1],acc[i][2],acc[i][3]);
                if(EPI==0) *reinterpret_cast<float4*>(&C[off])=v;
                else if(EPI==1){
                    float4 c=*reinterpret_cast<const float4*>(&C[off]);
                    c.x-=v.x; c.y-=v.y; c.z-=v.z; c.w-=v.w;
                    *reinterpret_cast<float4*>(&C[off])=c;
                } else if(EPI==2){
                    float4 c=*reinterpret_cast<const float4*>(&C0[off]);
                    c.x=fmaxf(c.x+v.x,0.f); c.y=fmaxf(c.y+v.y,0.f);
                    c.z=fmaxf(c.z+v.z,0.f); c.w=fmaxf(c.w+v.w,0.f);
                    *reinterpret_cast<float4*>(&C[off])=c;
                } else if(EPI==3){
                    float4 bb=*reinterpret_cast<const float4*>(&bias[n]);
                    v.x+=bb.x; v.y+=bb.y; v.z+=bb.z; v.w+=bb.w;
                    *reinterpret_cast<float4*>(&C[off])=v;
                    float4 r=make_float4(fmaxf(v.x,0.f),fmaxf(v.y,0.f),fmaxf(v.z,0.f),fmaxf(v.w,0.f));
                    *reinterpret_cast<float4*>(&C2[off])=r;
                } else {
                    *reinterpret_cast<float4*>(&C[off])=v;
                    // masked max: row m is head h, col n+j is modifier
                    if(m<=Lv){
                        #pragma unroll
                        for(int j=0;j<4;j++){
                            int mc=n+j;
                            if(mc>=1 && mc<=Lv && mc!=m) mx=fmaxf(mx,acc[i][j]);
                        }
                    }
                }
            }
        }
    }
    if(EPI==4){
        #pragma unroll
        for(int o=16;o>0;o>>=1) mx=fmaxf(mx,__shfl_xor_sync(0xffffffffu,mx,o));
        if((t&31)==0) atomicMax(pmax,fenc(mx));
    }
}

// ---------------- the mega kernel ----------------
__global__ void __launch_bounds__(256,2) mega_k(
    const float* __restrict__ Xh,const float* __restrict__ Xm,
    const int* __restrict__ len,
    const float* __restrict__ Wh,const float* __restrict__ bh,
    const float* __restrict__ Wm,const float* __restrict__ bm,
    const float* __restrict__ V,
    float* __restrict__ S,float* __restrict__ logZ,
    float* __restrict__ Y,float* __restrict__ entr)
{
    cg::grid_group grid=cg::this_grid();
    __shared__ USm sm;
    const int t=threadIdx.x;
    const int GB=gridDim.x;

    float *H0=g_H0,*M0=g_M0,*T1=g_T1,*T2=g_T2,*Lm=g_Lm,*Li=g_Li;
    float *Hc=g_Ha,*Mc=g_Ma,*Hx=g_Hb,*Mx=g_Mb;

    // ---- P0: H0 = Xh@Wh^T+bh (Ha=relu), M0 likewise ----
    for(int task=blockIdx.x;task<512;task+=GB){
        int which=task>>8, sub=task&255, mt=sub>>1, nt=sub&1;
        if(which==0)
            gemm_tile<false,true,3>(&sm,Xh,Wh,H0,nullptr,bh,Hc, mt*128,nt*64,BN,DH,DI,DI,DI,DH);
        else
            gemm_tile<false,true,3>(&sm,Xm,Wm,M0,nullptr,bm,Mc, mt*128,nt*64,BN,DH,DI,DI,DI,DH);
    }
    grid.sync();

    for(int it=0;it<10;it++){
        // ---- P1: T1 = Hc @ V  (+ reset score-max accumulators) ----
        for(int task=blockIdx.x;task<257;task+=GB){
            if(task<256){
                int mt=task>>1, nt=task&1;
                gemm_tile<false,false,0>(&sm,Hc,V,T1,nullptr,nullptr,nullptr,
                    mt*128,nt*64,BN,DH,DH,DH,DH,DH);
            } else {
                if(t<BB) g_pmInt[t]=0u;
            }
        }
        grid.sync();
        // ---- P2: S = T1 @ Mc^T (batched) with fused masked max ----
        for(int task=blockIdx.x;task<1024;task+=GB){
            int b=task>>5, s2=task&31, mt=s2>>3, nt=s2&7;
            gemm_tile<false,true,4>(&sm,T1+(long)b*NHS,Mc+(long)b*NHS,S+(long)b*SMAT,
                nullptr,nullptr,nullptr, mt*128,nt*64,NT,NT,DH,DH,DH,NT,
                len[b],&g_pmInt[b]);
        }
        grid.sync();
        // ---- P4: colsum+diag (tasks<64) and off-diag rows (64..319) ----
        for(int task=blockIdx.x;task<320;task+=GB){
            if(task<64){
                int b=task>>1, half=task&1;
                int L=len[b];
                float c=fdec(g_pmInt[b]);
                if(half==0 && t==0) g_c[b]=c;
                int j=half*256+t, m=j+1;
                const float* Sb=S+(long)b*SMAT;
                float* Lb=Lm+(long)b*SMAT;
                float cs=0.f;
                if(m>=1 && m<=L){
                    for(int h=0;h<=L;h++)
                        if(h!=m) cs+=expf(Sb[(long)h*NT+m]-c);
                }
                float dv;
                if(j==NT-1) dv=1.f;
                else {
                    float pad=(m>L)?1.f:0.f;
                    if(j==0){
                        float a=(m<=L)?expf(Sb[m]-c):0.f;
                        dv=a+pad;
                    } else dv=cs+pad;
                }
                Lb[(long)j*NT+j]=dv;
            } else {
                int t2=task-64;
                int b=t2>>3, rc=t2&7;
                int L=len[b]; float c=g_pmInt[b]?fdec(g_pmInt[b]):0.f;
                c=fdec(g_pmInt[b]);
                const float* Sb=S+(long)b*SMAT;
                float* Lb=Lm+(long)b*SMAT;
                for(int i=rc*64;i<rc*64+64;i++){
                    #pragma unroll
                    for(int w=0;w<2;w++){
                        int j=t+w*256;
                        if(j==i) continue;
                        float v;
                        if(i==NT-1 || j==NT-1) v=0.f;
                        else {
                            int m=j+1;
                            if(i==0) v=(m<=L)?expf(Sb[m]-c):0.f;
                            else {
                                int h=i+1;
                                v=(h<=L&&m<=L)? -expf(Sb[(long)h*NT+m]-c) : 0.f;
                            }
                        }
                        Lb[(long)i*NT+j]=v;
                    }
                }
            }
        }
        grid.sync();
        // ---- P5: blocked LU, 64-wide panels (8 panels) ----
        for(int k=0;k<8;k++){
            int k0=k*64, rem=NT-k0-64;
            // Phase A: redundant 64x64 diag factor + trsm roles
            for(int task=blockIdx.x;task<128;task+=GB){
                int b=task>>2, role=task&3;
                float* Lb=Lm+(long)b*SMAT;
                for(int i=t;i<4096;i+=256) sm.d.sd[i>>6][i&63]=Lb[(long)(k0+(i>>6))*NT+k0+(i&63)];
                __syncthreads();
                for(int j=0;j<63;j++){
                    if(t<64 && t>j){
                        float inv=1.f/sm.d.sd[j][j];
                        float l=sm.d.sd[t][j]*inv;
                        sm.d.sd[t][j]=l;
                        for(int jj=j+1;jj<64;jj++) sm.d.sd[t][jj]-=l*sm.d.sd[j][jj];
                    }
                    __syncthreads();
                }
                if(role==0){
                    for(int i=t;i<4096;i+=256) Lb[(long)(k0+(i>>6))*NT+k0+(i&63)]=sm.d.sd[i>>6][i&63];
                    if(t==0){
                        float s=0.f;
                        for(int j=0;j<64;j++) s+=logf(fabsf(sm.d.sd[j][j]));
                        g_ldp[b*8+k]=s;
                    }
                }
                if(role<2){
                    int row=k0+64+role*256+t;
                    if(row<NT){
                        float x[64];
                        #pragma unroll
                        for(int q=0;q<16;q++){
                            float4 v=*reinterpret_cast<const float4*>(&Lb[(long)row*NT+k0+q*4]);
                            x[q*4]=v.x; x[q*4+1]=v.y; x[q*4+2]=v.z; x[q*4+3]=v.w;
                        }
                        #pragma unroll
                        for(int j=0;j<64;j++){
                            float xj=x[j];
                            #pragma unroll
                            for(int l=0;l<64;l++) if(l<j) xj-=x[l]*sm.d.sd[l][j];
                            x[j]=xj/sm.d.sd[j][j];
                        }
                        #pragma unroll
                        for(int q=0;q<16;q++){
                            float4 v=make_float4(x[q*4],x[q*4+1],x[q*4+2],x[q*4+3]);
                            *reinterpret_cast<float4*>(&Lb[(long)row*NT+k0+q*4])=v;
                        }
                    }
                } else {
                    int cc=k0+64+(role-2)*256+t;
                    if(cc<NT){
                        float x[64];
                        #pragma unroll
                        for(int i=0;i<64;i++) x[i]=Lb[(long)(k0+i)*NT+cc];
                        #pragma unroll
                        for(int i=1;i<64;i++){
                            float xi=x[i];
                            #pragma unroll
                            for(int j=0;j<64;j++) if(j<i) xi-=sm.d.sd[i][j]*x[j];
                            x[i]=xi;
                        }
                        #pragma unroll
                        for(int i=0;i<64;i++) Lb[(long)(k0+i)*NT+cc]=x[i];
                    }
                }
                __syncthreads();
            }
            grid.sync();
            // Phase B: Schur update, K=64
            if(rem>0){
                int nbM=(rem+127)>>7, nbN=(rem+63)>>6;
                int ntasks=BB*nbM*nbN;
                for(int task=blockIdx.x;task<ntasks;task+=GB){
                    int b=task/(nbM*nbN), s2=task%(nbM*nbN), mt=s2/nbN, nt2=s2%nbN;
                    float* Lb=Lm+(long)b*SMAT;
                    gemm_tile<false,false,1>(&sm, Lb+(long)(k0+64)*NT+k0, Lb+(long)k0*NT+(k0+64),
                        Lb+(long)(k0+64)*NT+(k0+64), nullptr,nullptr,nullptr,
                        mt*128,nt2*64,rem,rem,64,NT,NT,NT);
                }
            }
            grid.sync();
        }
        // ---- P6: forward solve L Z = I (64-col stripes, 4-way kb parallel) ----
        for(int task=blockIdx.x;task<256;task+=GB){
            int b=task>>3, sI=task&7;
            const float* Lb=Lm+(long)b*SMAT;
            float* Zb=Li+(long)b*SMAT;
            int lc=t&63, grp=t>>6;
            int col=sI*64+lc;
            int start=2*sI;
            for(int ib=start;ib<16;ib++){
                float acc[32];
                #pragma unroll
                for(int r=0;r<32;r++) acc[r]=(grp==0 && ib*32+r==col)?1.f:0.f;
                int nkb=ib-start;
                for(int j0=0;j0<nkb;j0+=4){
                    int kb=start+j0+grp;
                    bool act=(kb<ib);
                    if(act){
                        for(int e=lc;e<1024;e+=64)
                            sm.s.T4[grp][e>>5][e&31]=Lb[(long)(ib*32+(e>>5))*NT + kb*32+(e&31)];
                    }
                    __syncthreads();
                    if(act){
                        #pragma unroll 4
                        for(int q=0;q<32;q++){
                            float xq=Zb[(long)(kb*32+q)*NT+col];
                            #pragma unroll
                            for(int r=0;r<32;r++) acc[r]-=sm.s.T4[grp][r][q]*xq;
                        }
                    }
                    __syncthreads();
                }
                if(grp>0){
                    #pragma unroll
                    for(int r=0;r<32;r++) sm.s.R[grp-1][r][lc]=acc[r];
                } else {
                    for(int e=lc;e<1024;e+=64)
                        sm.s.T4[0][e>>5][e&31]=Lb[(long)(ib*32+(e>>5))*NT + ib*32+(e&31)];
                }
                __syncthreads();
                if(grp==0){
                    #pragma unroll
                    for(int r=0;r<32;r++)
                        acc[r]+=sm.s.R[0][r][lc]+sm.s.R[1][r][lc]+sm.s.R[2][r][lc];
                    #pragma unroll
                    for(int r=1;r<32;r++){
                        float a=acc[r];
                        #pragma unroll
                        for(int q=0;q<32;q++) if(q<r) a-=sm.s.T4[0][r][q]*acc[q];
                        acc[r]=a;
                    }
                    #pragma unroll
                    for(int r=0;r<32;r++) Zb[(long)(ib*32+r)*NT+col]=acc[r];
                }
                __syncthreads();
            }
        }
        grid.sync();
        // ---- P7: backward solve U X = Z ----
        for(int task=blockIdx.x;task<256;task+=GB){
            int b=task>>3, sI=task&7;
            const float* Lb=Lm+(long)b*SMAT;
            float* Zb=Li+(long)b*SMAT;
            int lc=t&63, grp=t>>6;
            int col=sI*64+lc;
            int start=2*sI;
            for(int ib=15;ib>=0;ib--){
                float acc[32];
                if(grp==0 && ib>=start){
                    #pragma unroll
                    for(int r=0;r<32;r++) acc[r]=Zb[(long)(ib*32+r)*NT+col];
                } else {
                    #pragma unroll
                    for(int r=0;r<32;r++) acc[r]=0.f;
                }
                int nkb=15-ib;
                for(int j0=0;j0<nkb;j0+=4){
                    int kb=ib+1+j0+grp;
                    bool act=(kb<16);
                    if(act){
                        for(int e=lc;e<1024;e+=64)
                            sm.s.T4[grp][e>>5][e&31]=Lb[(long)(ib*32+(e>>5))*NT + kb*32+(e&31)];
                    }
                    __syncthreads();
                    if(act){
                        #pragma unroll 4
                        for(int q=0;q<32;q++){
                            float xq=Zb[(long)(kb*32+q)*NT+col];
                            #pragma unroll
                            for(int r=0;r<32;r++) acc[r]-=sm.s.T4[grp][r][q]*xq;
                        }
                    }
                    __syncthreads();
                }
                if(grp>0){
                    #pragma unroll
                    for(int r=0;r<32;r++) sm.s.R[grp-1][r][lc]=acc[r];
                } else {
                    for(int e=lc;e<1024;e+=64)
                        sm.s.T4[0][e>>5][e&31]=Lb[(long)(ib*32+(e>>5))*NT + ib*32+(e&31)];
                }
                __syncthreads();
                if(grp==0){
                    #pragma unroll
                    for(int r=0;r<32;r++)
                        acc[r]+=sm.s.R[0][r][lc]+sm.s.R[1][r][lc]+sm.s.R[2][r][lc];
                    #pragma unroll
                    for(int r=31;r>=0;r--){
                        float a=acc[r];
                        #pragma unroll
                        for(int q=0;q<32;q++) if(q>r) a-=sm.s.T4[0][r][q]*acc[q];
                        acc[r]=a/sm.s.T4[0][r][r];
                    }
                    #pragma unroll
                    for(int r=0;r<32;r++) Zb[(long)(ib*32+r)*NT+col]=acc[r];
                }
                __syncthreads();
            }
        }
        grid.sync();
        // ---- P8: marginals Y + entropy partials ----
        for(int task=blockIdx.x;task<8192;task+=GB){
            int b=task>>8, s2=task&255, hy=s2>>4, mxt=s2&15;
            int m0=mxt*32, h0=hy*32;
            const float* Lb=Li+(long)b*SMAT;
            const float* Sb=S+(long)b*SMAT;
            float* Yb=Y+(long)b*SMAT;
            int L=len[b]; float cb=g_c[b];
            for(int i=t;i<1024;i+=256){
                int mi=i>>5, hi=i&31;
                int m=m0+mi, h=h0+hi;
                sm.y.Lt[mi][hi]=(m>=1&&h>=1)? Lb[(long)(m-1)*NT+(h-1)] : 0.f;
            }
            if(t<32){
                int m=m0+t;
                sm.y.dg[t]=(m>=2)? Lb[(long)(m-1)*NT+(m-1)] : 0.f;
                sm.y.l0[t]=(m>=1)? Lb[(long)(m-1)*NT] : 0.f;
            }
            __syncthreads();
            float yts=0.f;
            int mi=t&31, hb2=t>>5;
            int m=m0+mi;
            #pragma unroll
            for(int p=0;p<4;p++){
                int hi=hb2+p*8;
                int h=h0+hi;
                float y=0.f;
                float sv=Sb[(long)h*NT+m];
                if(m>=1&&m<=L&&h<=L&&h!=m){
                    float a=expf(sv-cb);
                    float val=(h==0)? (sm.y.l0[mi]+sm.y.dg[mi])
                                    : (sm.y.dg[mi]-((h>=2)? sm.y.Lt[mi][hi]:0.f));
                    y=a*val; yts+=y*sv;
                }
                Yb[(long)h*NT+m]=y;
            }
            sm.y.red[t]=yts; __syncthreads();
            for(int s=128;s>0;s>>=1){ if(t<s) sm.y.red[t]+=sm.y.red[t+s]; __syncthreads(); }
            if(t==0) g_part[(long)b*256+hy*16+mxt]=sm.y.red[0];
            __syncthreads();
        }
        grid.sync();
        // ---- P9 (finalize) + P10 (feature GEMMs) fused ----
        int np=(it<9)? 544 : 32;
        for(int task=blockIdx.x;task<np;task+=GB){
            if(task<32){
                int b=task;
                sm.red[t]=g_part[(long)b*256+t];
                __syncthreads();
                for(int s=128;s>0;s>>=1){ if(t<s) sm.red[t]+=sm.red[t+s]; __syncthreads(); }
                if(t==0){
                    float ld=0.f;
                    for(int kk=0;kk<8;kk++) ld+=g_ldp[b*8+kk];
                    float lz=ld+(float)len[b]*g_c[b];
                    logZ[b]=lz; entr[b]=lz-sm.red[0];
                }
                __syncthreads();
            } else {
                int t2=task-32;
                int which=t2>>8, sub=t2&255;
                int b=sub>>3, s3=sub&7, mt=s3>>1, nt2=s3&1;
                if(which==0)
                    gemm_tile<false,false,0>(&sm,Y+(long)b*SMAT,Mc+(long)b*NHS,T1+(long)b*NHS,
                        nullptr,nullptr,nullptr, mt*128,nt2*64,NT,DH,NT,NT,DH,DH);
                else
                    gemm_tile<true,false,0>(&sm,Y+(long)b*SMAT,Hc+(long)b*NHS,T2+(long)b*NHS,
                        nullptr,nullptr,nullptr, mt*128,nt2*64,NT,DH,NT,NT,DH,DH);
            }
        }
        grid.sync();
        // ---- P11: Hx = relu(H0 + T1@V^T), Mx = relu(M0 + T2@V) ----
        if(it<9){
            for(int task=blockIdx.x;task<512;task+=GB){
                int which=task>>8, sub=task&255, mt=sub>>1, nt2=sub&1;
                if(which==0)
                    gemm_tile<false,true,2>(&sm,T1,V,Hx,H0,nullptr,nullptr,
                        mt*128,nt2*64,BN,DH,DH,DH,DH,DH);
                else
                    gemm_tile<false,false,2>(&sm,T2,V,Mx,M0,nullptr,nullptr,
                        mt*128,nt2*64,BN,DH,DH,DH,DH,DH);
            }
            grid.sync();
            float* tmp;
            tmp=Hc;Hc=Hx;Hx=tmp;
            tmp=Mc;Mc=Mx;Mx=tmp;
        }
    }
}

// ---------------- host launch ----------------
extern "C" void kernel_launch(void* const* d_in, const int* in_sizes, int n_in,
                              void* d_out, int out_size){
    const float* Xh=(const float*)d_in[0];
    const float* Xm=(const float*)d_in[1];
    const int*   len=(const int*)d_in[2];
    const float* Wh=(const float*)d_in[3];
    const float* bh=(const float*)d_in[4];
    const float* Wm=(const float*)d_in[5];
    const float* bm=(const float*)d_in[6];
    const float* V =(const float*)d_in[7];
    float* out=(float*)d_out;
    float* S   =out;
    float* logZ=out+(long)BB*SMAT;
    float* Y   =logZ+BB;
    float* entr=Y+(long)BB*SMAT;

    int dev=0; cudaGetDevice(&dev);
    int sms=0; cudaDeviceGetAttribute(&sms,cudaDevAttrMultiProcessorCount,dev);
    int occ=0; cudaOccupancyMaxActiveBlocksPerMultiprocessor(&occ,mega_k,256,0);
    if(occ<1) occ=1;
    int nblk=sms*occ;

    void* args[]={(void*)&Xh,(void*)&Xm,(void*)&len,(void*)&Wh,(void*)&bh,
                  (void*)&Wm,(void*)&bm,(void*)&V,
                  (void*)&S,(void*)&logZ,(void*)&Y,(void*)&entr};
    cudaLaunchCooperativeKernel((const void*)mega_k,dim3(nblk),dim3(256),args,0,(cudaStream_t)0);
}

// round 14
// speedup vs baseline: 2.2783x; 1.2719x over previous
#include <cuda_runtime.h>
#include <cooperative_groups.h>
#include <math.h>
namespace cg = cooperative_groups;

#define BB 32
#define NT 512
#define DH 128
#define DI 256
#define BN (BB*NT)
#define SMAT (NT*NT)
#define NHS ((long)NT*DH)

// ---------------- static device scratch ----------------
__device__ float g_H0[BN*DH];
__device__ float g_M0[BN*DH];
__device__ float g_Ha[BN*DH];
__device__ float g_Hb[BN*DH];
__device__ float g_Ma[BN*DH];
__device__ float g_Mb[BN*DH];
__device__ float g_T1[BN*DH];
__device__ float g_T2[BN*DH];
__device__ float g_Lm[(long)BB*SMAT];
__device__ float g_Li[(long)BB*SMAT];
__device__ float g_DL[(long)BB*8*4096];
__device__ float g_DU[(long)BB*8*4096];
__device__ float g_c[BB];
__device__ unsigned g_pmInt[BB];
__device__ float g_ldp[BB*8];
__device__ float g_part[BB*256];

// monotonic float<->uint encode for deterministic atomicMax
__device__ __forceinline__ unsigned fenc(float x){
    unsigned u=__float_as_uint(x);
    return (u&0x80000000u)? ~u : (u|0x80000000u);
}
__device__ __forceinline__ float fdec(unsigned u){
    unsigned b=(u&0x80000000u)? (u&0x7fffffffu) : ~u;
    return __uint_as_float(b);
}

// ---------------- shared memory union ----------------
// NOTE: Tm/Dm stride 68 (multiple of 4) so float4 loads of Tm rows are 16B-aligned.
struct SG { float As[2][16][132]; float Bs[2][16][68]; };
struct SE { float Tm[64][68]; float Dm[64][68]; };
struct SY { float Lt[32][33]; float dg[32]; float l0[32]; float red[256]; };
union USm { SG g; SE e; SY y; float red[256]; };

// ---------------- 128x64xK GEMM tile, double-buffered, float4, 256 thr ----------------
// EPI: 0 C=acc | 1 C-=acc | 2 C=relu(C0+acc) | 3 C=acc+bias,C2=relu(C) | 4 C=acc + masked atomic max
template<bool TRA,bool TRB,int EPI>
__device__ __forceinline__ void gemm_tile(USm* sm,
    const float* __restrict__ A,const float* __restrict__ B,
    float* __restrict__ C,const float* __restrict__ C0,
    const float* __restrict__ bias,float* __restrict__ C2,
    int m0,int n0,int M,int N,int K,int lda,int ldb,int ldc,
    int Lv=0, unsigned* pmax=nullptr)
{
    const int t=threadIdx.x;
    const int ty=t>>4, tx=t&15;
    float acc[8][4];
    #pragma unroll
    for(int i=0;i<8;i++)
        #pragma unroll
        for(int j=0;j<4;j++) acc[i][j]=0.f;

    const float4 z4=make_float4(0.f,0.f,0.f,0.f);
    auto ldA=[&](int kp,float4& v0,float4& v1){
        if(!TRA){
            int row=t>>1, kq=t&1;
            if(m0+row<M){
                const float* p=&A[(long)(m0+row)*lda + kp+kq*8];
                v0=*reinterpret_cast<const float4*>(p);
                v1=*reinterpret_cast<const float4*>(p+4);
            } else { v0=z4; v1=z4; }
        } else {
            int mq=t&31, kk=t>>5;
            int m=m0+mq*4;
            if(m<M){
                v0=*reinterpret_cast<const float4*>(&A[(long)(kp+kk)*lda + m]);
                v1=*reinterpret_cast<const float4*>(&A[(long)(kp+kk+8)*lda + m]);
            } else { v0=z4; v1=z4; }
        }
    };
    auto stA=[&](int buf,float4 v0,float4 v1){
        if(!TRA){
            int row=t>>1, kq=t&1;
            sm->g.As[buf][kq*8+0][row]=v0.x; sm->g.As[buf][kq*8+1][row]=v0.y;
            sm->g.As[buf][kq*8+2][row]=v0.z; sm->g.As[buf][kq*8+3][row]=v0.w;
            sm->g.As[buf][kq*8+4][row]=v1.x; sm->g.As[buf][kq*8+5][row]=v1.y;
            sm->g.As[buf][kq*8+6][row]=v1.z; sm->g.As[buf][kq*8+7][row]=v1.w;
        } else {
            int mq=t&31, kk=t>>5;
            *reinterpret_cast<float4*>(&sm->g.As[buf][kk][mq*4])=v0;
            *reinterpret_cast<float4*>(&sm->g.As[buf][kk+8][mq*4])=v1;
        }
    };
    auto ldB=[&](int kp)->float4{
        if(!TRB){
            int kk=t>>4, nq=t&15;
            if(n0+nq*4<N) return *reinterpret_cast<const float4*>(&B[(long)(kp+kk)*ldb + n0+nq*4]);
            return z4;
        } else {
            int row=t>>2, kq=t&3;
            if(n0+row<N) return *reinterpret_cast<const float4*>(&B[(long)(n0+row)*ldb + kp+kq*4]);
            return z4;
        }
    };
    auto stB=[&](int buf,float4 v){
        if(!TRB){
            int kk=t>>4, nq=t&15;
            *reinterpret_cast<float4*>(&sm->g.Bs[buf][kk][nq*4])=v;
        } else {
            int row=t>>2, kq=t&3;
            sm->g.Bs[buf][kq*4+0][row]=v.x; sm->g.Bs[buf][kq*4+1][row]=v.y;
            sm->g.Bs[buf][kq*4+2][row]=v.z; sm->g.Bs[buf][kq*4+3][row]=v.w;
        }
    };

    const int nk=K>>4;
    {
        float4 a0,a1; ldA(0,a0,a1);
        float4 b0=ldB(0);
        stA(0,a0,a1); stB(0,b0);
    }
    __syncthreads();
    for(int kb=0;kb<nk;kb++){
        int cur=kb&1;
        float4 pa0,pa1,pb;
        bool more=(kb+1<nk);
        if(more){ ldA((kb+1)<<4,pa0,pa1); pb=ldB((kb+1)<<4); }
        #pragma unroll
        for(int kk=0;kk<16;kk++){
            float4 a0=*reinterpret_cast<const float4*>(&sm->g.As[cur][kk][ty*8]);
            float4 a1=*reinterpret_cast<const float4*>(&sm->g.As[cur][kk][ty*8+4]);
            float4 b0=*reinterpret_cast<const float4*>(&sm->g.Bs[cur][kk][tx*4]);
            float a[8]={a0.x,a0.y,a0.z,a0.w,a1.x,a1.y,a1.z,a1.w};
            float b[4]={b0.x,b0.y,b0.z,b0.w};
            #pragma unroll
            for(int i=0;i<8;i++)
                #pragma unroll
                for(int j=0;j<4;j++) acc[i][j]=fmaf(a[i],b[j],acc[i][j]);
        }
        if(more){ stA(cur^1,pa0,pa1); stB(cur^1,pb); }
        __syncthreads();
    }
    float mx=-1e30f;
    int n=n0+tx*4;
    if(n<N){
        #pragma unroll
        for(int i=0;i<8;i++){
            int m=m0+ty*8+i;
            if(m<M){
                long off=(long)m*ldc+n;
                float4 v=make_float4(acc[i][0],acc[i][1],acc[i][2],acc[i][3]);
                if(EPI==0) *reinterpret_cast<float4*>(&C[off])=v;
                else if(EPI==1){
                    float4 c=*reinterpret_cast<const float4*>(&C[off]);
                    c.x-=v.x; c.y-=v.y; c.z-=v.z; c.w-=v.w;
                    *reinterpret_cast<float4*>(&C[off])=c;
                } else if(EPI==2){
                    float4 c=*reinterpret_cast<const float4*>(&C0[off]);
                    c.x=fmaxf(c.x+v.x,0.f); c.y=fmaxf(c.y+v.y,0.f);
                    c.z=fmaxf(c.z+v.z,0.f); c.w=fmaxf(c.w+v.w,0.f);
                    *reinterpret_cast<float4*>(&C[off])=c;
                } else if(EPI==3){
                    float4 bb=*reinterpret_cast<const float4*>(&bias[n]);
                    v.x+=bb.x; v.y+=bb.y; v.z+=bb.z; v.w+=bb.w;
                    *reinterpret_cast<float4*>(&C[off])=v;
                    float4 r=make_float4(fmaxf(v.x,0.f),fmaxf(v.y,0.f),fmaxf(v.z,0.f),fmaxf(v.w,0.f));
                    *reinterpret_cast<float4*>(&C2[off])=r;
                } else {
                    *reinterpret_cast<float4*>(&C[off])=v;
                    if(m<=Lv){
                        #pragma unroll
                        for(int j=0;j<4;j++){
                            int mc=n+j;
                            if(mc>=1 && mc<=Lv && mc!=m) mx=fmaxf(mx,acc[i][j]);
                        }
                    }
                }
            }
        }
    }
    if(EPI==4){
        #pragma unroll
        for(int o=16;o>0;o>>=1) mx=fmaxf(mx,__shfl_xor_sync(0xffffffffu,mx,o));
        if((t&31)==0) atomicMax(pmax,fenc(mx));
    }
}

// ---------------- 64x64xK tile with fused diag-inverse epilogue ----------------
// MODE 0: C=acc (plain). MODE 1: T=-acc; C=D*T. MODE 2: T=(C0?C0:0)-acc; C=D*T.
// No bounds checks: M=64 exact, N multiple of 64, K multiple of 16.
template<int MODE>
__device__ __forceinline__ void tile64(USm* sm,
    const float* __restrict__ A,const float* __restrict__ B,
    float* __restrict__ C,const float* __restrict__ C0,
    const float* __restrict__ Dg,
    int n0,int K,int lda,int ldb,int ldc)
{
    const int t=threadIdx.x;
    const int ty=t>>4, tx=t&15;
    float acc[4][4];
    #pragma unroll
    for(int i=0;i<4;i++)
        #pragma unroll
        for(int j=0;j<4;j++) acc[i][j]=0.f;

    const int nk=K>>4;
    if(nk>0){
        const int ar=t>>2, aq=t&3;
        const int bk=t>>4, bq=t&15;
        auto stA=[&](int buf,float4 v){
            sm->g.As[buf][aq*4+0][ar]=v.x; sm->g.As[buf][aq*4+1][ar]=v.y;
            sm->g.As[buf][aq*4+2][ar]=v.z; sm->g.As[buf][aq*4+3][ar]=v.w;
        };
        float4 a0=*reinterpret_cast<const float4*>(&A[(long)ar*lda + aq*4]);
        float4 b0=*reinterpret_cast<const float4*>(&B[(long)bk*ldb + n0+bq*4]);
        stA(0,a0);
        *reinterpret_cast<float4*>(&sm->g.Bs[0][bk][bq*4])=b0;
        __syncthreads();
        for(int kb=0;kb<nk;kb++){
            int cur=kb&1;
            float4 pa,pb;
            bool more=(kb+1<nk);
            if(more){
                int kp=(kb+1)<<4;
                pa=*reinterpret_cast<const float4*>(&A[(long)ar*lda + kp+aq*4]);
                pb=*reinterpret_cast<const float4*>(&B[(long)(kp+bk)*ldb + n0+bq*4]);
            }
            #pragma unroll
            for(int kk=0;kk<16;kk++){
                float4 a4=*reinterpret_cast<const float4*>(&sm->g.As[cur][kk][ty*4]);
                float4 b4=*reinterpret_cast<const float4*>(&sm->g.Bs[cur][kk][tx*4]);
                float a[4]={a4.x,a4.y,a4.z,a4.w};
                float b[4]={b4.x,b4.y,b4.z,b4.w};
                #pragma unroll
                for(int i=0;i<4;i++)
                    #pragma unroll
                    for(int j=0;j<4;j++) acc[i][j]=fmaf(a[i],b[j],acc[i][j]);
            }
            if(more){
                stA(cur^1,pa);
                *reinterpret_cast<float4*>(&sm->g.Bs[cur^1][bk][bq*4])=pb;
            }
            __syncthreads();
        }
    }
    if(MODE==0){
        #pragma unroll
        for(int i=0;i<4;i++){
            float4 v=make_float4(acc[i][0],acc[i][1],acc[i][2],acc[i][3]);
            *reinterpret_cast<float4*>(&C[(long)(ty*4+i)*ldc + n0+tx*4])=v;
        }
    } else {
        // stage T = init - acc
        #pragma unroll
        for(int i=0;i<4;i++){
            float4 c0=make_float4(0.f,0.f,0.f,0.f);
            if(MODE==2 && C0)
                c0=*reinterpret_cast<const float4*>(&C0[(long)(ty*4+i)*ldc + tx*4]);
            sm->e.Tm[ty*4+i][tx*4+0]=c0.x-acc[i][0];
            sm->e.Tm[ty*4+i][tx*4+1]=c0.y-acc[i][1];
            sm->e.Tm[ty*4+i][tx*4+2]=c0.z-acc[i][2];
            sm->e.Tm[ty*4+i][tx*4+3]=c0.w-acc[i][3];
        }
        for(int q=t;q<4096;q+=256) sm->e.Dm[q>>6][q&63]=Dg[q];
        __syncthreads();
        float o[4][4];
        #pragma unroll
        for(int i=0;i<4;i++)
            #pragma unroll
            for(int j=0;j<4;j++) o[i][j]=0.f;
        #pragma unroll 16
        for(int k=0;k<64;k++){
            float4 tv=*reinterpret_cast<const float4*>(&sm->e.Tm[k][tx*4]);
            float tvv[4]={tv.x,tv.y,tv.z,tv.w};
            #pragma unroll
            for(int i=0;i<4;i++){
                float d=sm->e.Dm[ty*4+i][k];
                #pragma unroll
                for(int j=0;j<4;j++) o[i][j]=fmaf(d,tvv[j],o[i][j]);
            }
        }
        __syncthreads();
        #pragma unroll
        for(int i=0;i<4;i++){
            float4 v=make_float4(o[i][0],o[i][1],o[i][2],o[i][3]);
            *reinterpret_cast<float4*>(&C[(long)(ty*4+i)*ldc + tx*4])=v;
        }
    }
}

// ---------------- the mega kernel ----------------
__global__ void __launch_bounds__(256,2) mega_k(
    const float* __restrict__ Xh,const float* __restrict__ Xm,
    const int* __restrict__ len,
    const float* __restrict__ Wh,const float* __restrict__ bh,
    const float* __restrict__ Wm,const float* __restrict__ bm,
    const float* __restrict__ V,
    float* __restrict__ S,float* __restrict__ logZ,
    float* __restrict__ Y,float* __restrict__ entr)
{
    cg::grid_group grid=cg::this_grid();
    __shared__ USm sm;
    const int t=threadIdx.x;
    const int GB=gridDim.x;

    float *H0=g_H0,*M0=g_M0,*T1=g_T1,*T2=g_T2,*Lm=g_Lm,*Li=g_Li;
    float *Hc=g_Ha,*Mc=g_Ma,*Hx=g_Hb,*Mx=g_Mb;

    // ---- P0 ----
    for(int task=blockIdx.x;task<512;task+=GB){
        int which=task>>8, sub=task&255, mt=sub>>1, nt=sub&1;
        if(which==0)
            gemm_tile<false,true,3>(&sm,Xh,Wh,H0,nullptr,bh,Hc, mt*128,nt*64,BN,DH,DI,DI,DI,DH);
        else
            gemm_tile<false,true,3>(&sm,Xm,Wm,M0,nullptr,bm,Mc, mt*128,nt*64,BN,DH,DI,DI,DI,DH);
    }
    grid.sync();

    for(int it=0;it<10;it++){
        // ---- P1: T1 = Hc @ V (+ reset max accumulators) ----
        for(int task=blockIdx.x;task<257;task+=GB){
            if(task<256){
                int mt=task>>1, nt=task&1;
                gemm_tile<false,false,0>(&sm,Hc,V,T1,nullptr,nullptr,nullptr,
                    mt*128,nt*64,BN,DH,DH,DH,DH,DH);
            } else {
                if(t<BB) g_pmInt[t]=0u;
            }
        }
        grid.sync();
        // ---- P2: S = T1 @ Mc^T with fused masked max ----
        for(int task=blockIdx.x;task<1024;task+=GB){
            int b=task>>5, s2=task&31, mt=s2>>3, nt=s2&7;
            gemm_tile<false,true,4>(&sm,T1+(long)b*NHS,Mc+(long)b*NHS,S+(long)b*SMAT,
                nullptr,nullptr,nullptr, mt*128,nt*64,NT,NT,DH,DH,DH,NT,
                len[b],&g_pmInt[b]);
        }
        grid.sync();
        // ---- P4: colsum+diag (tasks<64), off-diag rows (64..319) ----
        for(int task=blockIdx.x;task<320;task+=GB){
            if(task<64){
                int b=task>>1, half=task&1;
                int L=len[b];
                float c=fdec(g_pmInt[b]);
                if(half==0 && t==0) g_c[b]=c;
                int j=half*256+t, m=j+1;
                const float* Sb=S+(long)b*SMAT;
                float* Lb=Lm+(long)b*SMAT;
                float cs=0.f;
                if(m>=1 && m<=L){
                    for(int h=0;h<=L;h++)
                        if(h!=m) cs+=expf(Sb[(long)h*NT+m]-c);
                }
                float dv;
                if(j==NT-1) dv=1.f;
                else {
                    float pad=(m>L)?1.f:0.f;
                    if(j==0){
                        float a=(m<=L)?expf(Sb[m]-c):0.f;
                        dv=a+pad;
                    } else dv=cs+pad;
                }
                Lb[(long)j*NT+j]=dv;
            } else {
                int t2=task-64;
                int b=t2>>3, rc=t2&7;
                int L=len[b];
                float c=fdec(g_pmInt[b]);
                const float* Sb=S+(long)b*SMAT;
                float* Lb=Lm+(long)b*SMAT;
                for(int i=rc*64;i<rc*64+64;i++){
                    #pragma unroll
                    for(int w=0;w<2;w++){
                        int j=t+w*256;
                        if(j==i) continue;
                        float v;
                        if(i==NT-1 || j==NT-1) v=0.f;
                        else {
                            int m=j+1;
                            if(i==0) v=(m<=L)?expf(Sb[m]-c):0.f;
                            else {
                                int h=i+1;
                                v=(h<=L&&m<=L)? -expf(Sb[(long)h*NT+m]-c) : 0.f;
                            }
                        }
                        Lb[(long)i*NT+j]=v;
                    }
                }
            }
        }
        grid.sync();
        // ---- P5: blocked LU with explicit diag inverses ----
        for(int k=0;k<8;k++){
            int k0=k*64, rem=NT-k0-64;
            // A1: factor diag + invert L11,U11 (32 tasks)
            for(int task=blockIdx.x;task<32;task+=GB){
                int b=task;
                float* Lb=Lm+(long)b*SMAT;
                float (*sd)[68]=sm.e.Tm;
                for(int q=t;q<4096;q+=256) sd[q>>6][q&63]=Lb[(long)(k0+(q>>6))*NT + k0+(q&63)];
                __syncthreads();
                for(int j=0;j<63;j++){
                    if(t<64 && t>j){
                        float inv=1.f/sd[j][j];
                        float l=sd[t][j]*inv;
                        sd[t][j]=l;
                        for(int jj=j+1;jj<64;jj++) sd[t][jj]-=l*sd[j][jj];
                    }
                    __syncthreads();
                }
                if(t==0){
                    float s=0.f;
                    for(int j=0;j<64;j++) s+=logf(fabsf(sd[j][j]));
                    g_ldp[b*8+k]=s;
                }
                if(t<64){
                    // Linv column t (unit lower)
                    float x[64];
                    #pragma unroll
                    for(int r=0;r<64;r++) x[r]=(r==t)?1.f:0.f;
                    #pragma unroll
                    for(int r=1;r<64;r++){
                        float s2=x[r];
                        #pragma unroll
                        for(int l=0;l<64;l++) if(l<r) s2-=sd[r][l]*x[l];
                        x[r]=s2;
                    }
                    float* DLp=g_DL+((long)b*8+k)*4096;
                    #pragma unroll
                    for(int r=0;r<64;r++) DLp[r*64+t]=x[r];
                } else if(t<128){
                    // Uinv column cc
                    int cc=t-64;
                    float x[64];
                    #pragma unroll
                    for(int r=0;r<64;r++) x[r]=(r==cc)?1.f:0.f;
                    #pragma unroll
                    for(int r=63;r>=0;r--){
                        float s2=x[r];
                        #pragma unroll
                        for(int l=0;l<64;l++) if(l>r) s2-=sd[r][l]*x[l];
                        x[r]=s2/sd[r][r];
                    }
                    float* DUp=g_DU+((long)b*8+k)*4096;
                    #pragma unroll
                    for(int r=0;r<64;r++) DUp[r*64+cc]=x[r];
                }
                __syncthreads();
            }
            grid.sync();
            if(rem>0){
                // A2: L21 = A21*U11inv (128-tiles), U12 = L11inv*A12 (64-tiles)
                int nbL=(rem+127)>>7, nbU=rem>>6;
                int per=nbL+nbU;
                int ntask=BB*per;
                for(int task=blockIdx.x;task<ntask;task+=GB){
                    int b=task/per, s2=task%per;
                    float* Lb=Lm+(long)b*SMAT;
                    if(s2<nbL){
                        gemm_tile<false,false,0>(&sm, Lb+(long)(k0+64)*NT+k0,
                            g_DU+((long)b*8+k)*4096,
                            Lb+(long)(k0+64)*NT+k0, nullptr,nullptr,nullptr,
                            s2*128,0,rem,64,64,NT,64,NT);
                    } else {
                        int u=s2-nbL;
                        tile64<0>(&sm, g_DL+((long)b*8+k)*4096,
                            Lb+(long)k0*NT+(k0+64),
                            Lb+(long)k0*NT+(k0+64), nullptr,nullptr,
                            u*64,64,64,NT,NT);
                    }
                }
                grid.sync();
                // B: Schur
                int nbM=(rem+127)>>7, nbN=rem>>6;
                int ntasks=BB*nbM*nbN;
                for(int task=blockIdx.x;task<ntasks;task+=GB){
                    int b=task/(nbM*nbN), s2=task%(nbM*nbN), mt=s2/nbN, nt2=s2%nbN;
                    float* Lb=Lm+(long)b*SMAT;
                    gemm_tile<false,false,1>(&sm, Lb+(long)(k0+64)*NT+k0, Lb+(long)k0*NT+(k0+64),
                        Lb+(long)(k0+64)*NT+(k0+64), nullptr,nullptr,nullptr,
                        mt*128,nt2*64,rem,rem,64,NT,NT,NT);
                }
                grid.sync();
            }
        }
        // ---- P6: forward Z = L^{-1} (blocked, GEMM + fused Linv multiply) ----
        for(int ib=0;ib<8;ib++){
            int ntask=BB*(ib+1);
            for(int task=blockIdx.x;task<ntask;task+=GB){
                int b=task/(ib+1), jb=task%(ib+1);
                float* Zb=Li+(long)b*SMAT;
                const float* Lb=Lm+(long)b*SMAT;
                const float* DL=g_DL+((long)b*8+ib)*4096;
                if(jb==ib){
                    for(int q=t;q<4096;q+=256)
                        Zb[(long)(ib*64+(q>>6))*NT + ib*64+(q&63)] = DL[q];
                } else {
                    tile64<1>(&sm, Lb+(long)(ib*64)*NT + jb*64,
                        Zb+(long)(jb*64)*NT + jb*64,
                        Zb+(long)(ib*64)*NT + jb*64, nullptr, DL,
                        0,(ib-jb)*64, NT,NT,NT);
                }
            }
            grid.sync();
        }
        // ---- P7: backward X = U^{-1} Z (Z upper blocks are implicit zero) ----
        for(int ib=7;ib>=0;ib--){
            for(int task=blockIdx.x;task<256;task+=GB){
                int b=task>>3, jb=task&7;
                float* Zb=Li+(long)b*SMAT;
                const float* Lb=Lm+(long)b*SMAT;
                const float* DU=g_DU+((long)b*8+ib)*4096;
                float* Ct=Zb+(long)(ib*64)*NT + jb*64;
                const float* C0=(jb<=ib)? Ct : nullptr;
                tile64<2>(&sm, Lb+(long)(ib*64)*NT + (ib+1)*64,
                    Zb+(long)((ib+1)*64)*NT + jb*64,
                    Ct, C0, DU,
                    0,(7-ib)*64, NT,NT,NT);
            }
            grid.sync();
        }
        // ---- P8: marginals Y + entropy partials ----
        for(int task=blockIdx.x;task<8192;task+=GB){
            int b=task>>8, s2=task&255, hy=s2>>4, mxt=s2&15;
            int m0=mxt*32, h0=hy*32;
            const float* Lb=Li+(long)b*SMAT;
            const float* Sb=S+(long)b*SMAT;
            float* Yb=Y+(long)b*SMAT;
            int L=len[b]; float cb=g_c[b];
            for(int i=t;i<1024;i+=256){
                int mi=i>>5, hi=i&31;
                int m=m0+mi, h=h0+hi;
                sm.y.Lt[mi][hi]=(m>=1&&h>=1)? Lb[(long)(m-1)*NT+(h-1)] : 0.f;
            }
            if(t<32){
                int m=m0+t;
                sm.y.dg[t]=(m>=2)? Lb[(long)(m-1)*NT+(m-1)] : 0.f;
                sm.y.l0[t]=(m>=1)? Lb[(long)(m-1)*NT] : 0.f;
            }
            __syncthreads();
            float yts=0.f;
            int mi=t&31, hb2=t>>5;
            int m=m0+mi;
            #pragma unroll
            for(int p=0;p<4;p++){
                int hi=hb2+p*8;
                int h=h0+hi;
                float y=0.f;
                float sv=Sb[(long)h*NT+m];
                if(m>=1&&m<=L&&h<=L&&h!=m){
                    float a=expf(sv-cb);
                    float val=(h==0)? (sm.y.l0[mi]+sm.y.dg[mi])
                                    : (sm.y.dg[mi]-((h>=2)? sm.y.Lt[mi][hi]:0.f));
                    y=a*val; yts+=y*sv;
                }
                Yb[(long)h*NT+m]=y;
            }
            sm.y.red[t]=yts; __syncthreads();
            for(int s=128;s>0;s>>=1){ if(t<s) sm.y.red[t]+=sm.y.red[t+s]; __syncthreads(); }
            if(t==0) g_part[(long)b*256+hy*16+mxt]=sm.y.red[0];
            __syncthreads();
        }
        grid.sync();
        // ---- P9 (finalize) + P10 (feature GEMMs) fused ----
        int np=(it<9)? 544 : 32;
        for(int task=blockIdx.x;task<np;task+=GB){
            if(task<32){
                int b=task;
                sm.red[t]=g_part[(long)b*256+t];
                __syncthreads();
                for(int s=128;s>0;s>>=1){ if(t<s) sm.red[t]+=sm.red[t+s]; __syncthreads(); }
                if(t==0){
                    float ld=0.f;
                    for(int kk=0;kk<8;kk++) ld+=g_ldp[b*8+kk];
                    float lz=ld+(float)len[b]*g_c[b];
                    logZ[b]=lz; entr[b]=lz-sm.red[0];
                }
                __syncthreads();
            } else {
                int t2=task-32;
                int which=t2>>8, sub=t2&255;
                int b=sub>>3, s3=sub&7, mt=s3>>1, nt2=s3&1;
                if(which==0)
                    gemm_tile<false,false,0>(&sm,Y+(long)b*SMAT,Mc+(long)b*NHS,T1+(long)b*NHS,
                        nullptr,nullptr,nullptr, mt*128,nt2*64,NT,DH,NT,NT,DH,DH);
                else
                    gemm_tile<true,false,0>(&sm,Y+(long)b*SMAT,Hc+(long)b*NHS,T2+(long)b*NHS,
                        nullptr,nullptr,nullptr, mt*128,nt2*64,NT,DH,NT,NT,DH,DH);
            }
        }
        grid.sync();
        // ---- P11 ----
        if(it<9){
            for(int task=blockIdx.x;task<512;task+=GB){
                int which=task>>8, sub=task&255, mt=sub>>1, nt2=sub&1;
                if(which==0)
                    gemm_tile<false,true,2>(&sm,T1,V,Hx,H0,nullptr,nullptr,
                        mt*128,nt2*64,BN,DH,DH,DH,DH,DH);
                else
                    gemm_tile<false,false,2>(&sm,T2,V,Mx,M0,nullptr,nullptr,
                        mt*128,nt2*64,BN,DH,DH,DH,DH,DH);
            }
            grid.sync();
            float* tmp;
            tmp=Hc;Hc=Hx;Hx=tmp;
            tmp=Mc;Mc=Mx;Mx=tmp;
        }
    }
}

// ---------------- host launch ----------------
extern "C" void kernel_launch(void* const* d_in, const int* in_sizes, int n_in,
                              void* d_out, int out_size){
    const float* Xh=(const float*)d_in[0];
    const float* Xm=(const float*)d_in[1];
    const int*   len=(const int*)d_in[2];
    const float* Wh=(const float*)d_in[3];
    const float* bh=(const float*)d_in[4];
    const float* Wm=(const float*)d_in[5];
    const float* bm=(const float*)d_in[6];
    const float* V =(const float*)d_in[7];
    float* out=(float*)d_out;
    float* S   =out;
    float* logZ=out+(long)BB*SMAT;
    float* Y   =logZ+BB;
    float* entr=Y+(long)BB*SMAT;

    int dev=0; cudaGetDevice(&dev);
    int sms=0; cudaDeviceGetAttribute(&sms,cudaDevAttrMultiProcessorCount,dev);
    int occ=0; cudaOccupancyMaxActiveBlocksPerMultiprocessor(&occ,mega_k,256,0);
    if(occ<1) occ=1;
    int nblk=sms*occ;

    void* args[]={(void*)&Xh,(void*)&Xm,(void*)&len,(void*)&Wh,(void*)&bh,
                  (void*)&Wm,(void*)&bm,(void*)&V,
                  (void*)&S,(void*)&logZ,(void*)&Y,(void*)&entr};
    cudaLaunchCooperativeKernel((const void*)mega_k,dim3(nblk),dim3(256),args,0,(cudaStream_t)0);
}